// round 1
// baseline (speedup 1.0000x reference)
#include <cuda_runtime.h>
#include <cuda_bf16.h>

// Problem constants
#define BNC    2
#define SQ     2048
#define DMODEL 1024
#define NH     16
#define DKH    64
#define MROWS  (BNC * SQ)   // 4096

// Scratch (device globals; no allocation allowed)
__device__ float g_q[MROWS * DMODEL];
__device__ float g_k[MROWS * DMODEL];
__device__ float g_v[MROWS * DMODEL];
__device__ float g_ctx[MROWS * DMODEL];

// ---------------------------------------------------------------------------
// GEMM: C[M,N] = A[M,K] @ W[N,K]^T + bias   (torch Linear convention)
// M=4096, N=1024, K=1024. Block tile 128x64, k-tile 32, 256 threads, 8x4 micro.
// Operands staged transposed in smem ([k][m] / [k][n]) so compute-side reads
// are conflict-free float4.
// HEAD_LAYOUT=1: write [B,H,S,DK]; 0: plain [M,N].
// ---------------------------------------------------------------------------
template <int HEAD_LAYOUT>
__global__ __launch_bounds__(256)
void gemm_bias_kernel(const float* __restrict__ A, const float* __restrict__ W,
                      const float* __restrict__ bias, float* __restrict__ C)
{
    __shared__ float As[32][132];  // [k][m], pad 4 (float4-aligned rows)
    __shared__ float Bs[32][68];   // [k][n]

    const int tid = threadIdx.x;
    const int tx  = tid & 15;      // 0..15  -> n micro
    const int ty  = tid >> 4;      // 0..15  -> m micro
    const int m0  = blockIdx.y * 128;
    const int n0  = blockIdx.x * 64;

    const int lm  = tid >> 3;          // 0..31 (load row)
    const int lk4 = (tid & 7) << 2;    // 0,4,...,28 (load k offset)

    float acc[8][4];
#pragma unroll
    for (int i = 0; i < 8; i++)
#pragma unroll
        for (int j = 0; j < 4; j++) acc[i][j] = 0.f;

    for (int k0 = 0; k0 < DMODEL; k0 += 32) {
        // A tile 128x32 -> As[k][m]
#pragma unroll
        for (int it = 0; it < 4; it++) {
            const int m = lm + it * 32;
            float4 v = *reinterpret_cast<const float4*>(&A[(size_t)(m0 + m) * DMODEL + k0 + lk4]);
            As[lk4 + 0][m] = v.x; As[lk4 + 1][m] = v.y;
            As[lk4 + 2][m] = v.z; As[lk4 + 3][m] = v.w;
        }
        // W tile 64x32 -> Bs[k][n]
#pragma unroll
        for (int it = 0; it < 2; it++) {
            const int n = lm + it * 32;
            float4 v = *reinterpret_cast<const float4*>(&W[(size_t)(n0 + n) * DMODEL + k0 + lk4]);
            Bs[lk4 + 0][n] = v.x; Bs[lk4 + 1][n] = v.y;
            Bs[lk4 + 2][n] = v.z; Bs[lk4 + 3][n] = v.w;
        }
        __syncthreads();

#pragma unroll
        for (int k = 0; k < 32; k++) {
            float4 a0 = *reinterpret_cast<const float4*>(&As[k][ty * 8]);
            float4 a1 = *reinterpret_cast<const float4*>(&As[k][ty * 8 + 4]);
            float4 bb = *reinterpret_cast<const float4*>(&Bs[k][tx * 4]);
            float av[8] = {a0.x, a0.y, a0.z, a0.w, a1.x, a1.y, a1.z, a1.w};
            float bv[4] = {bb.x, bb.y, bb.z, bb.w};
#pragma unroll
            for (int i = 0; i < 8; i++)
#pragma unroll
                for (int j = 0; j < 4; j++) acc[i][j] += av[i] * bv[j];
        }
        __syncthreads();
    }

#pragma unroll
    for (int i = 0; i < 8; i++) {
        const int m = m0 + ty * 8 + i;
#pragma unroll
        for (int j = 0; j < 4; j++) {
            const int n  = n0 + tx * 4 + j;
            const float val = acc[i][j] + bias[n];
            if (HEAD_LAYOUT) {
                const int b = m >> 11, s = m & (SQ - 1);
                const int h = n >> 6, d = n & (DKH - 1);
                C[(((size_t)(b * NH + h) * SQ) + s) * DKH + d] = val;
            } else {
                C[(size_t)m * DMODEL + n] = val;
            }
        }
    }
}

// ---------------------------------------------------------------------------
// Flash attention (fp32): per (b,h), 64-query tile, loops 64-key tiles.
// Q pre-scaled by 1/sqrt(dk). Online softmax in registers; P staged through
// the K smem buffer for the PV GEMM. Writes context in [B,S,D] layout.
// Dynamic smem: Qs[64][68] + KPs[64][68] + Vs[64][64] = 51200 B.
// ---------------------------------------------------------------------------
#define ATTN_SMEM_FLOATS (64 * 68 * 2 + 64 * 64)

__global__ __launch_bounds__(256)
void flash_attn_kernel()
{
    extern __shared__ float sm[];
    float* Qs  = sm;                 // [64][68]
    float* KPs = sm + 64 * 68;       // [64][68]  K^T ([d][n]) then P ([r][kk])
    float* Vs  = sm + 2 * 64 * 68;   // [64][64]  [n][d]

    const int tid = threadIdx.x;
    const int tx  = tid & 15;
    const int ty  = tid >> 4;
    const int row = ty * 4;
    const int col = tx * 4;

    const int m0 = blockIdx.x * 64;
    const int h  = blockIdx.y;
    const int b  = blockIdx.z;
    const int bh = b * NH + h;

    const float* Qg = g_q + ((size_t)bh * SQ + m0) * DKH;
    const float* Kg = g_k + (size_t)bh * SQ * DKH;
    const float* Vg = g_v + (size_t)bh * SQ * DKH;

    // Load Q tile (pre-scaled by 1/8): 64x64 floats, float4
    {
        const int r  = tid >> 4;          // 0..15
        const int c4 = (tid & 15) * 4;
#pragma unroll
        for (int it = 0; it < 4; it++) {
            float4 v = *reinterpret_cast<const float4*>(&Qg[(size_t)(r + it * 16) * DKH + c4]);
            v.x *= 0.125f; v.y *= 0.125f; v.z *= 0.125f; v.w *= 0.125f;
            *reinterpret_cast<float4*>(&Qs[(r + it * 16) * 68 + c4]) = v;
        }
    }

    float acc[4][4];
#pragma unroll
    for (int i = 0; i < 4; i++)
#pragma unroll
        for (int j = 0; j < 4; j++) acc[i][j] = 0.f;
    float mrow[4], lrow[4];
#pragma unroll
    for (int i = 0; i < 4; i++) { mrow[i] = -1e30f; lrow[i] = 0.f; }

    for (int n0 = 0; n0 < SQ; n0 += 64) {
        __syncthreads();  // previous PV reads of KPs/Vs complete (and Qs visible, iter 0)

        // K tile -> KPs[d][n] (transposed), V tile -> Vs[n][d]
        {
            const int r  = tid >> 4;
            const int c4 = (tid & 15) * 4;
#pragma unroll
            for (int it = 0; it < 4; it++) {
                const int n = r + it * 16;
                float4 kv = *reinterpret_cast<const float4*>(&Kg[(size_t)(n0 + n) * DKH + c4]);
                KPs[(c4 + 0) * 68 + n] = kv.x;
                KPs[(c4 + 1) * 68 + n] = kv.y;
                KPs[(c4 + 2) * 68 + n] = kv.z;
                KPs[(c4 + 3) * 68 + n] = kv.w;
                float4 vv = *reinterpret_cast<const float4*>(&Vg[(size_t)(n0 + n) * DKH + c4]);
                *reinterpret_cast<float4*>(&Vs[n * 64 + c4]) = vv;
            }
        }
        __syncthreads();

        // S = Q @ K^T (already scaled)
        float s[4][4];
#pragma unroll
        for (int i = 0; i < 4; i++)
#pragma unroll
            for (int j = 0; j < 4; j++) s[i][j] = 0.f;
#pragma unroll
        for (int k = 0; k < 64; k++) {
            float4 kb = *reinterpret_cast<const float4*>(&KPs[k * 68 + col]);
            const float kv[4] = {kb.x, kb.y, kb.z, kb.w};
#pragma unroll
            for (int i = 0; i < 4; i++) {
                const float q = Qs[(row + i) * 68 + k];
#pragma unroll
                for (int j = 0; j < 4; j++) s[i][j] += q * kv[j];
            }
        }

        // online softmax (row reduce across 16 lanes sharing the row group)
#pragma unroll
        for (int i = 0; i < 4; i++) {
            float rmax = fmaxf(fmaxf(s[i][0], s[i][1]), fmaxf(s[i][2], s[i][3]));
#pragma unroll
            for (int off = 8; off; off >>= 1)
                rmax = fmaxf(rmax, __shfl_xor_sync(0xffffffffu, rmax, off));
            const float mn    = fmaxf(mrow[i], rmax);
            const float alpha = __expf(mrow[i] - mn);
            mrow[i] = mn;
            float rsum = 0.f;
#pragma unroll
            for (int j = 0; j < 4; j++) {
                const float p = __expf(s[i][j] - mn);
                s[i][j] = p;
                rsum += p;
            }
#pragma unroll
            for (int off = 8; off; off >>= 1)
                rsum += __shfl_xor_sync(0xffffffffu, rsum, off);
            lrow[i] = lrow[i] * alpha + rsum;
#pragma unroll
            for (int j = 0; j < 4; j++) acc[i][j] *= alpha;
        }

        __syncthreads();  // all done reading KPs as K^T
        // stage P into KPs as [r][kk]
#pragma unroll
        for (int i = 0; i < 4; i++) {
            float4 p4 = make_float4(s[i][0], s[i][1], s[i][2], s[i][3]);
            *reinterpret_cast<float4*>(&KPs[(row + i) * 68 + col]) = p4;
        }
        __syncthreads();

        // O += P @ V
#pragma unroll
        for (int kk = 0; kk < 64; kk++) {
            float4 vb = *reinterpret_cast<const float4*>(&Vs[kk * 64 + col]);
            const float vv[4] = {vb.x, vb.y, vb.z, vb.w};
#pragma unroll
            for (int i = 0; i < 4; i++) {
                const float p = KPs[(row + i) * 68 + kk];
#pragma unroll
                for (int j = 0; j < 4; j++) acc[i][j] += p * vv[j];
            }
        }
    }

    // finalize: divide by l, write context [B,S,D]
#pragma unroll
    for (int i = 0; i < 4; i++) {
        const float inv = 1.f / lrow[i];
        float4 o = make_float4(acc[i][0] * inv, acc[i][1] * inv,
                               acc[i][2] * inv, acc[i][3] * inv);
        const size_t gm = (size_t)b * SQ + m0 + row + i;
        *reinterpret_cast<float4*>(&g_ctx[gm * DMODEL + h * DKH + col]) = o;
    }
}

// ---------------------------------------------------------------------------
extern "C" void kernel_launch(void* const* d_in, const int* in_sizes, int n_in,
                              void* d_out, int out_size)
{
    const float* q  = (const float*)d_in[0];
    const float* k  = (const float*)d_in[1];
    const float* v  = (const float*)d_in[2];
    const float* Wq = (const float*)d_in[3];
    const float* bq = (const float*)d_in[4];
    const float* Wk = (const float*)d_in[5];
    const float* bk = (const float*)d_in[6];
    const float* Wv = (const float*)d_in[7];
    const float* bv = (const float*)d_in[8];
    const float* Wo = (const float*)d_in[9];
    const float* bo = (const float*)d_in[10];
    float* out = (float*)d_out;

    float *gq, *gk, *gv, *gctx;
    cudaGetSymbolAddress((void**)&gq,   g_q);
    cudaGetSymbolAddress((void**)&gk,   g_k);
    cudaGetSymbolAddress((void**)&gv,   g_v);
    cudaGetSymbolAddress((void**)&gctx, g_ctx);

    const size_t attn_smem = ATTN_SMEM_FLOATS * sizeof(float);  // 51200 B
    cudaFuncSetAttribute(flash_attn_kernel,
                         cudaFuncAttributeMaxDynamicSharedMemorySize, (int)attn_smem);

    dim3 gemm_grid(DMODEL / 64, MROWS / 128);   // (16, 32)
    dim3 gemm_blk(256);

    // QKV projections -> [B,H,S,DK]
    gemm_bias_kernel<1><<<gemm_grid, gemm_blk>>>(q, Wq, bq, gq);
    gemm_bias_kernel<1><<<gemm_grid, gemm_blk>>>(k, Wk, bk, gk);
    gemm_bias_kernel<1><<<gemm_grid, gemm_blk>>>(v, Wv, bv, gv);

    // attention -> context [B,S,D]
    dim3 attn_grid(SQ / 64, NH, BNC);           // (32, 16, 2)
    flash_attn_kernel<<<attn_grid, 256, attn_smem>>>();

    // output projection -> d_out [B,S,D]
    gemm_bias_kernel<0><<<gemm_grid, gemm_blk>>>(gctx, Wo, bo, out);
}

// round 3
// speedup vs baseline: 1.4671x; 1.4671x over previous
#include <cuda_runtime.h>
#include <cuda_bf16.h>
#include <cstdint>

// Problem constants
#define BNC    2
#define SQ     2048
#define DMODEL 1024
#define NH     16
#define DKH    64
#define MROWS  (BNC * SQ)   // 4096
#define K3     (3 * DMODEL) // 3072 split-K

// Scratch (device globals; no allocation allowed)
__device__ float g_q[MROWS * DMODEL];
__device__ float g_k[MROWS * DMODEL];
__device__ float g_v[MROWS * DMODEL];
__device__ float g_ctx[MROWS * DMODEL];
__device__ __nv_bfloat16 g_splitA[MROWS * K3];   // 24 MB
__device__ __nv_bfloat16 g_splitB[DMODEL * K3];  // 6 MB

// ============================================================================
// PTX helpers (compute_103-safe: mma.sync / ldmatrix / cp.async only)
// ============================================================================
__device__ __forceinline__ uint32_t smem_u32(const void* p) {
    uint32_t a;
    asm("{ .reg .u64 t; cvta.to.shared.u64 t, %1; cvt.u32.u64 %0, t; }" : "=r"(a) : "l"(p));
    return a;
}
__device__ __forceinline__ void cp_async16(uint32_t dst, const void* src) {
    asm volatile("cp.async.cg.shared.global [%0], [%1], 16;" :: "r"(dst), "l"(src));
}
#define CP_COMMIT() asm volatile("cp.async.commit_group;" ::: "memory")
#define CP_WAIT(n)  asm volatile("cp.async.wait_group %0;" :: "n"(n) : "memory")

#define LDSM_X4(r0, r1, r2, r3, addr) \
    asm volatile("ldmatrix.sync.aligned.m8n8.x4.shared.b16 {%0,%1,%2,%3}, [%4];" \
                 : "=r"(r0), "=r"(r1), "=r"(r2), "=r"(r3) : "r"(addr))

#define MMA_BF16(c0, c1, c2, c3, a0, a1, a2, a3, b0, b1) \
    asm volatile("mma.sync.aligned.m16n8k16.row.col.f32.bf16.bf16.f32 " \
                 "{%0,%1,%2,%3}, {%4,%5,%6,%7}, {%8,%9}, {%0,%1,%2,%3};" \
                 : "+f"(c0), "+f"(c1), "+f"(c2), "+f"(c3) \
                 : "r"(a0), "r"(a1), "r"(a2), "r"(a3), "r"(b0), "r"(b1))

// ============================================================================
// Split conversion: x -> (hi=bf16(x), lo=bf16(x-hi)), laid out along 3K.
// PAT=0 (A): [hi | lo | hi]    PAT=1 (W): [hi | hi | lo]
// (hi*hi + lo*hi + hi*lo) == exact product to ~2^-16 per term, fp32 accum.
// ============================================================================
template <int PAT>
__global__ __launch_bounds__(256)
void split_kernel(const float* __restrict__ src, __nv_bfloat16* __restrict__ dst)
{
    const int idx4 = blockIdx.x * 256 + threadIdx.x;
    const int r  = idx4 >> 8;
    const int k4 = (idx4 & 255) << 2;
    float4 x = *reinterpret_cast<const float4*>(&src[(size_t)r * DMODEL + k4]);

    __nv_bfloat16 h0 = __float2bfloat16(x.x), h1 = __float2bfloat16(x.y);
    __nv_bfloat16 h2 = __float2bfloat16(x.z), h3 = __float2bfloat16(x.w);
    __nv_bfloat16 l0 = __float2bfloat16(x.x - __bfloat162float(h0));
    __nv_bfloat16 l1 = __float2bfloat16(x.y - __bfloat162float(h1));
    __nv_bfloat16 l2 = __float2bfloat16(x.z - __bfloat162float(h2));
    __nv_bfloat16 l3 = __float2bfloat16(x.w - __bfloat162float(h3));

    __nv_bfloat162 hA = __nv_bfloat162(h0, h1), hB = __nv_bfloat162(h2, h3);
    __nv_bfloat162 lA = __nv_bfloat162(l0, l1), lB = __nv_bfloat162(l2, l3);

    const size_t base = (size_t)r * K3 + k4;
    __nv_bfloat162* p0 = reinterpret_cast<__nv_bfloat162*>(&dst[base]);
    __nv_bfloat162* p1 = reinterpret_cast<__nv_bfloat162*>(&dst[base + DMODEL]);
    __nv_bfloat162* p2 = reinterpret_cast<__nv_bfloat162*>(&dst[base + 2 * DMODEL]);
    p0[0] = hA; p0[1] = hB;
    if (PAT == 0) { p1[0] = lA; p1[1] = lB; p2[0] = hA; p2[1] = hB; }
    else          { p1[0] = hA; p1[1] = hB; p2[0] = lA; p2[1] = lB; }
}

// ============================================================================
// HMMA GEMM: C[4096,1024] = A'[4096,3072] @ B'[1024,3072]^T + bias
// CTA 128x128, 8 warps (2x4), warp tile 64x32. K-chunk 64 bf16 (128 B rows,
// XOR-swizzled). 3-stage cp.async pipeline. mma.sync m16n8k16 bf16->fp32.
// LAYOUT=1: write [B,H,S,DK]; 0: plain [M,1024].
// ============================================================================
#define TM 128
#define TN 128
#define KC 64
#define NT (K3 / KC)                  // 48 k-chunks
#define NS 3                          // pipeline stages
#define STAGE_BYTES ((TM + TN) * 128) // 32768
#define GEMM_SMEM   (NS * STAGE_BYTES)

template <int LAYOUT>
__global__ __launch_bounds__(256, 1)
void gemm_tc_kernel(const __nv_bfloat16* __restrict__ A,
                    const __nv_bfloat16* __restrict__ B,
                    const float* __restrict__ bias,
                    float* __restrict__ C)
{
    extern __shared__ __align__(1024) char smem[];
    const uint32_t sb = smem_u32(smem);
    const int tid  = threadIdx.x;
    const int wid  = tid >> 5;
    const int lane = tid & 31;
    const int wm   = wid >> 2;         // 0..1  (64-row slab)
    const int wn   = wid & 3;          // 0..3  (32-col slab)
    const int n0   = blockIdx.x * TN;
    const int m0   = blockIdx.y * TM;

    const char* Abase = reinterpret_cast<const char*>(A) + (size_t)m0 * (K3 * 2);
    const char* Bbase = reinterpret_cast<const char*>(B) + (size_t)n0 * (K3 * 2);

    // loader: k-chunk c into stage s. 256 combined rows (128 A + 128 B) x 8 segs.
    auto load_chunk = [&](int c, int s) {
        const uint32_t st = sb + s * STAGE_BYTES;
        const int koff = c * 128;      // byte offset along K
#pragma unroll
        for (int i = 0; i < 8; i++) {
            const int idx = tid + i * 256;
            const int row = idx >> 3, seg = idx & 7;
            const uint32_t dst = st + row * 128 + ((seg ^ (row & 7)) << 4);
            const char* src = (row < TM)
                ? Abase + (size_t)row * (K3 * 2) + koff + seg * 16
                : Bbase + (size_t)(row - TM) * (K3 * 2) + koff + seg * 16;
            cp_async16(dst, src);
        }
        CP_COMMIT();
    };

    float acc[4][4][4];   // [mtile][ntile8][frag]
#pragma unroll
    for (int i = 0; i < 4; i++)
#pragma unroll
        for (int j = 0; j < 4; j++)
#pragma unroll
            for (int f = 0; f < 4; f++) acc[i][j][f] = 0.f;

    // prologue
    load_chunk(0, 0);
    load_chunk(1, 1);

    // precomputed ldmatrix lane-row components
    const int a_row  = wm * 64 + (lane & 15);        // + i*16
    const int a_kseg = (lane >> 4);                  // + ks*2
    const int b_row  = wn * 32 + ((lane & 7) | ((lane & 16) >> 1)); // + j2*16
    const int b_kseg = (lane & 8) >> 3;              // + ks*2

    for (int kt = 0; kt < NT; kt++) {
        if (kt == NT - 1) { CP_WAIT(0); } else { CP_WAIT(1); }
        __syncthreads();

        const uint32_t st = sb + (kt % NS) * STAGE_BYTES;
        const uint32_t sBm = st + TM * 128;

#pragma unroll
        for (int ks = 0; ks < 4; ks++) {
            uint32_t af[4][4];
#pragma unroll
            for (int i = 0; i < 4; i++) {
                const int row = a_row + i * 16;
                const uint32_t addr = st + row * 128 + (((a_kseg + ks * 2) ^ (row & 7)) << 4);
                LDSM_X4(af[i][0], af[i][1], af[i][2], af[i][3], addr);
            }
            uint32_t bf[2][4];
#pragma unroll
            for (int j2 = 0; j2 < 2; j2++) {
                const int row = b_row + j2 * 16;
                const uint32_t addr = sBm + (row - TM) * 128 + TM * 128
                                    + (((b_kseg + ks * 2) ^ (row & 7)) << 4);
                // note: row here is absolute within combined 256-row region? No:
                // b_row is 0..31 (+16) within B tile; recompute cleanly below.
                (void)addr;
                const int brow = b_row + j2 * 16;  // 0..47 within B tile
                const uint32_t baddr = sBm + brow * 128 + (((b_kseg + ks * 2) ^ (brow & 7)) << 4);
                LDSM_X4(bf[j2][0], bf[j2][1], bf[j2][2], bf[j2][3], baddr);
            }
#pragma unroll
            for (int i = 0; i < 4; i++) {
#pragma unroll
                for (int j2 = 0; j2 < 2; j2++) {
                    MMA_BF16(acc[i][j2 * 2 + 0][0], acc[i][j2 * 2 + 0][1],
                             acc[i][j2 * 2 + 0][2], acc[i][j2 * 2 + 0][3],
                             af[i][0], af[i][1], af[i][2], af[i][3],
                             bf[j2][0], bf[j2][1]);
                    MMA_BF16(acc[i][j2 * 2 + 1][0], acc[i][j2 * 2 + 1][1],
                             acc[i][j2 * 2 + 1][2], acc[i][j2 * 2 + 1][3],
                             af[i][0], af[i][1], af[i][2], af[i][3],
                             bf[j2][2], bf[j2][3]);
                }
            }
        }

        if (kt + NS - 1 < NT) load_chunk(kt + NS - 1, (kt + NS - 1) % NS);
    }

    // Epilogue: regs -> gmem with bias. Thread (l) in tile(i,j):
    // rows m0+wm*64+i*16+l/4 (+8), cols n0+wn*32+j*8+(l%4)*2 (+1)
    const int crow = m0 + wm * 64 + (lane >> 2);
    const int ccol = n0 + wn * 32 + (lane & 3) * 2;
#pragma unroll
    for (int i = 0; i < 4; i++) {
#pragma unroll
        for (int j = 0; j < 4; j++) {
            const int col = ccol + j * 8;
            const float2 bv = *reinterpret_cast<const float2*>(&bias[col]);
#pragma unroll
            for (int rh = 0; rh < 2; rh++) {
                const int m = crow + i * 16 + rh * 8;
                float2 v;
                v.x = acc[i][j][rh * 2 + 0] + bv.x;
                v.y = acc[i][j][rh * 2 + 1] + bv.y;
                float* dst;
                if (LAYOUT == 1) {
                    const int b = m >> 11, ss = m & (SQ - 1);
                    const int h = col >> 6, d = col & (DKH - 1);
                    dst = C + (((size_t)(b * NH + h) * SQ + ss) * DKH + d);
                } else {
                    dst = C + (size_t)m * DMODEL + col;
                }
                *reinterpret_cast<float2*>(dst) = v;
            }
        }
    }
}

// ---------------------------------------------------------------------------
// Flash attention (fp32) — unchanged (fp32 issue roofline; tensor next round).
// ---------------------------------------------------------------------------
#define ATTN_SMEM_FLOATS (64 * 68 * 2 + 64 * 64)

__global__ __launch_bounds__(256)
void flash_attn_kernel()
{
    extern __shared__ float sm[];
    float* Qs  = sm;
    float* KPs = sm + 64 * 68;
    float* Vs  = sm + 2 * 64 * 68;

    const int tid = threadIdx.x;
    const int tx  = tid & 15;
    const int ty  = tid >> 4;
    const int row = ty * 4;
    const int col = tx * 4;

    const int m0 = blockIdx.x * 64;
    const int h  = blockIdx.y;
    const int b  = blockIdx.z;
    const int bh = b * NH + h;

    const float* Qg = g_q + ((size_t)bh * SQ + m0) * DKH;
    const float* Kg = g_k + (size_t)bh * SQ * DKH;
    const float* Vg = g_v + (size_t)bh * SQ * DKH;

    {
        const int r  = tid >> 4;
        const int c4 = (tid & 15) * 4;
#pragma unroll
        for (int it = 0; it < 4; it++) {
            float4 v = *reinterpret_cast<const float4*>(&Qg[(size_t)(r + it * 16) * DKH + c4]);
            v.x *= 0.125f; v.y *= 0.125f; v.z *= 0.125f; v.w *= 0.125f;
            *reinterpret_cast<float4*>(&Qs[(r + it * 16) * 68 + c4]) = v;
        }
    }

    float acc[4][4];
#pragma unroll
    for (int i = 0; i < 4; i++)
#pragma unroll
        for (int j = 0; j < 4; j++) acc[i][j] = 0.f;
    float mrow[4], lrow[4];
#pragma unroll
    for (int i = 0; i < 4; i++) { mrow[i] = -1e30f; lrow[i] = 0.f; }

    for (int n0 = 0; n0 < SQ; n0 += 64) {
        __syncthreads();
        {
            const int r  = tid >> 4;
            const int c4 = (tid & 15) * 4;
#pragma unroll
            for (int it = 0; it < 4; it++) {
                const int n = r + it * 16;
                float4 kv = *reinterpret_cast<const float4*>(&Kg[(size_t)(n0 + n) * DKH + c4]);
                KPs[(c4 + 0) * 68 + n] = kv.x;
                KPs[(c4 + 1) * 68 + n] = kv.y;
                KPs[(c4 + 2) * 68 + n] = kv.z;
                KPs[(c4 + 3) * 68 + n] = kv.w;
                float4 vv = *reinterpret_cast<const float4*>(&Vg[(size_t)(n0 + n) * DKH + c4]);
                *reinterpret_cast<float4*>(&Vs[n * 64 + c4]) = vv;
            }
        }
        __syncthreads();

        float s[4][4];
#pragma unroll
        for (int i = 0; i < 4; i++)
#pragma unroll
            for (int j = 0; j < 4; j++) s[i][j] = 0.f;
#pragma unroll
        for (int k = 0; k < 64; k++) {
            float4 kb = *reinterpret_cast<const float4*>(&KPs[k * 68 + col]);
            const float kv[4] = {kb.x, kb.y, kb.z, kb.w};
#pragma unroll
            for (int i = 0; i < 4; i++) {
                const float q = Qs[(row + i) * 68 + k];
#pragma unroll
                for (int j = 0; j < 4; j++) s[i][j] += q * kv[j];
            }
        }

#pragma unroll
        for (int i = 0; i < 4; i++) {
            float rmax = fmaxf(fmaxf(s[i][0], s[i][1]), fmaxf(s[i][2], s[i][3]));
#pragma unroll
            for (int off = 8; off; off >>= 1)
                rmax = fmaxf(rmax, __shfl_xor_sync(0xffffffffu, rmax, off));
            const float mn    = fmaxf(mrow[i], rmax);
            const float alpha = __expf(mrow[i] - mn);
            mrow[i] = mn;
            float rsum = 0.f;
#pragma unroll
            for (int j = 0; j < 4; j++) {
                const float p = __expf(s[i][j] - mn);
                s[i][j] = p;
                rsum += p;
            }
#pragma unroll
            for (int off = 8; off; off >>= 1)
                rsum += __shfl_xor_sync(0xffffffffu, rsum, off);
            lrow[i] = lrow[i] * alpha + rsum;
#pragma unroll
            for (int j = 0; j < 4; j++) acc[i][j] *= alpha;
        }

        __syncthreads();
#pragma unroll
        for (int i = 0; i < 4; i++) {
            float4 p4 = make_float4(s[i][0], s[i][1], s[i][2], s[i][3]);
            *reinterpret_cast<float4*>(&KPs[(row + i) * 68 + col]) = p4;
        }
        __syncthreads();

#pragma unroll
        for (int kk = 0; kk < 64; kk++) {
            float4 vb = *reinterpret_cast<const float4*>(&Vs[kk * 64 + col]);
            const float vv[4] = {vb.x, vb.y, vb.z, vb.w};
#pragma unroll
            for (int i = 0; i < 4; i++) {
                const float p = KPs[(row + i) * 68 + kk];
#pragma unroll
                for (int j = 0; j < 4; j++) acc[i][j] += p * vv[j];
            }
        }
    }

#pragma unroll
    for (int i = 0; i < 4; i++) {
        const float inv = 1.f / lrow[i];
        float4 o = make_float4(acc[i][0] * inv, acc[i][1] * inv,
                               acc[i][2] * inv, acc[i][3] * inv);
        const size_t gm = (size_t)b * SQ + m0 + row + i;
        *reinterpret_cast<float4*>(&g_ctx[gm * DMODEL + h * DKH + col]) = o;
    }
}

// ---------------------------------------------------------------------------
extern "C" void kernel_launch(void* const* d_in, const int* in_sizes, int n_in,
                              void* d_out, int out_size)
{
    const float* q  = (const float*)d_in[0];
    const float* k  = (const float*)d_in[1];
    const float* v  = (const float*)d_in[2];
    const float* Wq = (const float*)d_in[3];
    const float* bq = (const float*)d_in[4];
    const float* Wk = (const float*)d_in[5];
    const float* bk = (const float*)d_in[6];
    const float* Wv = (const float*)d_in[7];
    const float* bv = (const float*)d_in[8];
    const float* Wo = (const float*)d_in[9];
    const float* bo = (const float*)d_in[10];
    float* out = (float*)d_out;

    float *gq, *gk, *gv, *gctx;
    __nv_bfloat16 *sA, *sB;
    cudaGetSymbolAddress((void**)&gq,   g_q);
    cudaGetSymbolAddress((void**)&gk,   g_k);
    cudaGetSymbolAddress((void**)&gv,   g_v);
    cudaGetSymbolAddress((void**)&gctx, g_ctx);
    cudaGetSymbolAddress((void**)&sA,   g_splitA);
    cudaGetSymbolAddress((void**)&sB,   g_splitB);

    const size_t attn_smem = ATTN_SMEM_FLOATS * sizeof(float);
    cudaFuncSetAttribute(flash_attn_kernel,
                         cudaFuncAttributeMaxDynamicSharedMemorySize, (int)attn_smem);
    cudaFuncSetAttribute(gemm_tc_kernel<0>,
                         cudaFuncAttributeMaxDynamicSharedMemorySize, GEMM_SMEM);
    cudaFuncSetAttribute(gemm_tc_kernel<1>,
                         cudaFuncAttributeMaxDynamicSharedMemorySize, GEMM_SMEM);

    const dim3 gemm_grid(DMODEL / TN, MROWS / TM);         // (8, 32)
    const int  splitA_blocks = MROWS * DMODEL / 4 / 256;   // 4096
    const int  splitW_blocks = DMODEL * DMODEL / 4 / 256;  // 1024

    // Q projection
    split_kernel<0><<<splitA_blocks, 256>>>(q, sA);
    split_kernel<1><<<splitW_blocks, 256>>>(Wq, sB);
    gemm_tc_kernel<1><<<gemm_grid, 256, GEMM_SMEM>>>(sA, sB, bq, gq);
    // K projection
    split_kernel<0><<<splitA_blocks, 256>>>(k, sA);
    split_kernel<1><<<splitW_blocks, 256>>>(Wk, sB);
    gemm_tc_kernel<1><<<gemm_grid, 256, GEMM_SMEM>>>(sA, sB, bk, gk);
    // V projection
    split_kernel<0><<<splitA_blocks, 256>>>(v, sA);
    split_kernel<1><<<splitW_blocks, 256>>>(Wv, sB);
    gemm_tc_kernel<1><<<gemm_grid, 256, GEMM_SMEM>>>(sA, sB, bv, gv);

    // attention
    dim3 attn_grid(SQ / 64, NH, BNC);
    flash_attn_kernel<<<attn_grid, 256, attn_smem>>>();

    // output projection
    split_kernel<0><<<splitA_blocks, 256>>>(gctx, sA);
    split_kernel<1><<<splitW_blocks, 256>>>(Wo, sB);
    gemm_tc_kernel<0><<<gemm_grid, 256, GEMM_SMEM>>>(sA, sB, bo, out);
}

// round 4
// speedup vs baseline: 2.9181x; 1.9891x over previous
#include <cuda_runtime.h>
#include <cuda_bf16.h>
#include <cstdint>

// Problem constants
#define BNC    2
#define SQ     2048
#define DMODEL 1024
#define NH     16
#define DKH    64
#define MROWS  (BNC * SQ)   // 4096
#define K3     (3 * DMODEL) // 3072 split-K

// Scratch (device globals; no allocation allowed)
__device__ float g_ctx[MROWS * DMODEL];
__device__ __nv_bfloat16 g_splitA[MROWS * K3];   // 24 MB
__device__ __nv_bfloat16 g_splitB[DMODEL * K3];  // 6 MB
__device__ __nv_bfloat16 g_qh[MROWS * DMODEL];   // [B,H,S,64], pre-scaled 1/8
__device__ __nv_bfloat16 g_ql[MROWS * DMODEL];
__device__ __nv_bfloat16 g_kh[MROWS * DMODEL];   // [B,H,S,64]
__device__ __nv_bfloat16 g_kl[MROWS * DMODEL];
__device__ __nv_bfloat16 g_vth[MROWS * DMODEL];  // [B,H,64,S] (V transposed)
__device__ __nv_bfloat16 g_vtl[MROWS * DMODEL];

// ============================================================================
// PTX helpers (compute_103-safe)
// ============================================================================
__device__ __forceinline__ uint32_t smem_u32(const void* p) {
    uint32_t a;
    asm("{ .reg .u64 t; cvta.to.shared.u64 t, %1; cvt.u32.u64 %0, t; }" : "=r"(a) : "l"(p));
    return a;
}
__device__ __forceinline__ void cp_async16(uint32_t dst, const void* src) {
    asm volatile("cp.async.cg.shared.global [%0], [%1], 16;" :: "r"(dst), "l"(src));
}
#define CP_COMMIT() asm volatile("cp.async.commit_group;" ::: "memory")
#define CP_WAIT(n)  asm volatile("cp.async.wait_group %0;" :: "n"(n) : "memory")

#define LDSM_X4(r0, r1, r2, r3, addr) \
    asm volatile("ldmatrix.sync.aligned.m8n8.x4.shared.b16 {%0,%1,%2,%3}, [%4];" \
                 : "=r"(r0), "=r"(r1), "=r"(r2), "=r"(r3) : "r"(addr))

#define MMA_BF16(c0, c1, c2, c3, a0, a1, a2, a3, b0, b1) \
    asm volatile("mma.sync.aligned.m16n8k16.row.col.f32.bf16.bf16.f32 " \
                 "{%0,%1,%2,%3}, {%4,%5,%6,%7}, {%8,%9}, {%0,%1,%2,%3};" \
                 : "+f"(c0), "+f"(c1), "+f"(c2), "+f"(c3) \
                 : "r"(a0), "r"(a1), "r"(a2), "r"(a3), "r"(b0), "r"(b1))

__device__ __forceinline__ uint32_t pack_bf16(float a, float b) {
    __nv_bfloat162 t = __float22bfloat162_rn(make_float2(a, b));
    return *reinterpret_cast<uint32_t*>(&t);
}
__device__ __forceinline__ float2 unpack_bf16(uint32_t r) {
    __nv_bfloat162 t = *reinterpret_cast<__nv_bfloat162*>(&r);
    return __bfloat1622float2(t);
}

// ============================================================================
// Split conversion (for GEMM A/W operands): x -> hi/lo bf16 along 3K.
// PAT=0 (A): [hi | lo | hi]    PAT=1 (W): [hi | hi | lo]
// ============================================================================
template <int PAT>
__global__ __launch_bounds__(256)
void split_kernel(const float* __restrict__ src, __nv_bfloat16* __restrict__ dst)
{
    const int idx4 = blockIdx.x * 256 + threadIdx.x;
    const int r  = idx4 >> 8;
    const int k4 = (idx4 & 255) << 2;
    float4 x = *reinterpret_cast<const float4*>(&src[(size_t)r * DMODEL + k4]);

    __nv_bfloat16 h0 = __float2bfloat16(x.x), h1 = __float2bfloat16(x.y);
    __nv_bfloat16 h2 = __float2bfloat16(x.z), h3 = __float2bfloat16(x.w);
    __nv_bfloat16 l0 = __float2bfloat16(x.x - __bfloat162float(h0));
    __nv_bfloat16 l1 = __float2bfloat16(x.y - __bfloat162float(h1));
    __nv_bfloat16 l2 = __float2bfloat16(x.z - __bfloat162float(h2));
    __nv_bfloat16 l3 = __float2bfloat16(x.w - __bfloat162float(h3));

    __nv_bfloat162 hA = __nv_bfloat162(h0, h1), hB = __nv_bfloat162(h2, h3);
    __nv_bfloat162 lA = __nv_bfloat162(l0, l1), lB = __nv_bfloat162(l2, l3);

    const size_t base = (size_t)r * K3 + k4;
    __nv_bfloat162* p0 = reinterpret_cast<__nv_bfloat162*>(&dst[base]);
    __nv_bfloat162* p1 = reinterpret_cast<__nv_bfloat162*>(&dst[base + DMODEL]);
    __nv_bfloat162* p2 = reinterpret_cast<__nv_bfloat162*>(&dst[base + 2 * DMODEL]);
    p0[0] = hA; p0[1] = hB;
    if (PAT == 0) { p1[0] = lA; p1[1] = lB; p2[0] = hA; p2[1] = hB; }
    else          { p1[0] = hA; p1[1] = hB; p2[0] = lA; p2[1] = lB; }
}

// ============================================================================
// HMMA GEMM: C[4096,1024] = A'[4096,3072] @ B'[1024,3072]^T + bias
// MODE 0: fp32 [M,1024]    MODE 2: Q split bf16 head layout, scale 1/8
// MODE 3: K split bf16 head layout    MODE 4: V split bf16 transposed
// ============================================================================
#define TM 128
#define TN 128
#define NT (K3 / 64)                  // 48 k-chunks
#define NS 3
#define STAGE_BYTES ((TM + TN) * 128) // 32768
#define GEMM_SMEM   (NS * STAGE_BYTES)

template <int MODE>
__global__ __launch_bounds__(256, 1)
void gemm_tc_kernel(const __nv_bfloat16* __restrict__ A,
                    const __nv_bfloat16* __restrict__ B,
                    const float* __restrict__ bias,
                    float* __restrict__ C,
                    __nv_bfloat16* __restrict__ OH,
                    __nv_bfloat16* __restrict__ OL)
{
    extern __shared__ __align__(1024) char smem[];
    const uint32_t sb = smem_u32(smem);
    const int tid  = threadIdx.x;
    const int wid  = tid >> 5;
    const int lane = tid & 31;
    const int wm   = wid >> 2;
    const int wn   = wid & 3;
    const int n0   = blockIdx.x * TN;
    const int m0   = blockIdx.y * TM;

    const char* Abase = reinterpret_cast<const char*>(A) + (size_t)m0 * (K3 * 2);
    const char* Bbase = reinterpret_cast<const char*>(B) + (size_t)n0 * (K3 * 2);

    auto load_chunk = [&](int c, int s) {
        const uint32_t st = sb + s * STAGE_BYTES;
        const int koff = c * 128;
#pragma unroll
        for (int i = 0; i < 8; i++) {
            const int idx = tid + i * 256;
            const int row = idx >> 3, seg = idx & 7;
            const uint32_t dst = st + row * 128 + ((seg ^ (row & 7)) << 4);
            const char* src = (row < TM)
                ? Abase + (size_t)row * (K3 * 2) + koff + seg * 16
                : Bbase + (size_t)(row - TM) * (K3 * 2) + koff + seg * 16;
            cp_async16(dst, src);
        }
        CP_COMMIT();
    };

    float acc[4][4][4];
#pragma unroll
    for (int i = 0; i < 4; i++)
#pragma unroll
        for (int j = 0; j < 4; j++)
#pragma unroll
            for (int f = 0; f < 4; f++) acc[i][j][f] = 0.f;

    load_chunk(0, 0);
    load_chunk(1, 1);

    const int a_row  = wm * 64 + (lane & 15);
    const int a_kseg = (lane >> 4);
    const int b_row  = wn * 32 + ((lane & 7) | ((lane & 16) >> 1));
    const int b_kseg = (lane & 8) >> 3;

    for (int kt = 0; kt < NT; kt++) {
        if (kt == NT - 1) { CP_WAIT(0); } else { CP_WAIT(1); }
        __syncthreads();

        const uint32_t st  = sb + (kt % NS) * STAGE_BYTES;
        const uint32_t sBm = st + TM * 128;

#pragma unroll
        for (int ks = 0; ks < 4; ks++) {
            uint32_t af[4][4];
#pragma unroll
            for (int i = 0; i < 4; i++) {
                const int row = a_row + i * 16;
                const uint32_t addr = st + row * 128 + (((a_kseg + ks * 2) ^ (row & 7)) << 4);
                LDSM_X4(af[i][0], af[i][1], af[i][2], af[i][3], addr);
            }
            uint32_t bf[2][4];
#pragma unroll
            for (int j2 = 0; j2 < 2; j2++) {
                const int brow = b_row + j2 * 16;
                const uint32_t baddr = sBm + brow * 128 + (((b_kseg + ks * 2) ^ (brow & 7)) << 4);
                LDSM_X4(bf[j2][0], bf[j2][1], bf[j2][2], bf[j2][3], baddr);
            }
#pragma unroll
            for (int i = 0; i < 4; i++) {
#pragma unroll
                for (int j2 = 0; j2 < 2; j2++) {
                    MMA_BF16(acc[i][j2 * 2 + 0][0], acc[i][j2 * 2 + 0][1],
                             acc[i][j2 * 2 + 0][2], acc[i][j2 * 2 + 0][3],
                             af[i][0], af[i][1], af[i][2], af[i][3],
                             bf[j2][0], bf[j2][1]);
                    MMA_BF16(acc[i][j2 * 2 + 1][0], acc[i][j2 * 2 + 1][1],
                             acc[i][j2 * 2 + 1][2], acc[i][j2 * 2 + 1][3],
                             af[i][0], af[i][1], af[i][2], af[i][3],
                             bf[j2][2], bf[j2][3]);
                }
            }
        }

        if (kt + NS - 1 < NT) load_chunk(kt + NS - 1, (kt + NS - 1) % NS);
    }

    const int crow = m0 + wm * 64 + (lane >> 2);
    const int ccol = n0 + wn * 32 + (lane & 3) * 2;
#pragma unroll
    for (int i = 0; i < 4; i++) {
#pragma unroll
        for (int j = 0; j < 4; j++) {
            const int col = ccol + j * 8;
            const float2 bv = *reinterpret_cast<const float2*>(&bias[col]);
#pragma unroll
            for (int rh = 0; rh < 2; rh++) {
                const int m = crow + i * 16 + rh * 8;
                float2 v;
                v.x = acc[i][j][rh * 2 + 0] + bv.x;
                v.y = acc[i][j][rh * 2 + 1] + bv.y;
                if (MODE == 0) {
                    *reinterpret_cast<float2*>(&C[(size_t)m * DMODEL + col]) = v;
                } else {
                    if (MODE == 2) { v.x *= 0.125f; v.y *= 0.125f; }
                    __nv_bfloat162 hi = __float22bfloat162_rn(v);
                    float2 hf = __bfloat1622float2(hi);
                    __nv_bfloat162 lo = __float22bfloat162_rn(
                        make_float2(v.x - hf.x, v.y - hf.y));
                    const int b = m >> 11, s = m & (SQ - 1);
                    const int h = col >> 6, d = col & (DKH - 1);
                    if (MODE == 4) {
                        // transposed: [B,H,64,S]
                        const size_t t0 = (((size_t)(b * NH + h) * DKH + d) * SQ + s);
                        const size_t t1 = t0 + SQ;
                        OH[t0] = hi.x; OH[t1] = hi.y;
                        OL[t0] = lo.x; OL[t1] = lo.y;
                    } else {
                        const size_t a0 = (((size_t)(b * NH + h) * SQ + s) * DKH + d);
                        *reinterpret_cast<__nv_bfloat162*>(&OH[a0]) = hi;
                        *reinterpret_cast<__nv_bfloat162*>(&OL[a0]) = lo;
                    }
                }
            }
        }
    }
}

// ============================================================================
// Flash attention, HMMA bf16 3-term splits. Br=128 (8 warps x 16 rows), Bc=64.
// SMEM: Qh/Ql [128][64] (32 KB) + 2 stages x {Kh,Kl,Vth,Vtl [64][64]} (64 KB).
// ============================================================================
#define BR 128
#define BC 64
#define NTK (SQ / BC)        // 32
#define AT_QBYTES   16384
#define AT_STAGE    32768
#define ATTN_SMEM   (2 * AT_QBYTES + 2 * AT_STAGE)   // 98304

__global__ __launch_bounds__(256, 2)
void flash_hmma_kernel()
{
    extern __shared__ __align__(1024) char smem[];
    const uint32_t sb = smem_u32(smem);
    const int tid  = threadIdx.x;
    const int wid  = tid >> 5;
    const int lane = tid & 31;

    const int m0 = blockIdx.x * BR;
    const int h  = blockIdx.y;
    const int b  = blockIdx.z;
    const int bh = b * NH + h;

    const __nv_bfloat16* qh_g  = g_qh  + ((size_t)bh * SQ + m0) * DKH;
    const __nv_bfloat16* ql_g  = g_ql  + ((size_t)bh * SQ + m0) * DKH;
    const __nv_bfloat16* kh_g  = g_kh  + (size_t)bh * SQ * DKH;
    const __nv_bfloat16* kl_g  = g_kl  + (size_t)bh * SQ * DKH;
    const __nv_bfloat16* vth_g = g_vth + (size_t)bh * DKH * SQ;
    const __nv_bfloat16* vtl_g = g_vtl + (size_t)bh * DKH * SQ;

    // ---- load Q (hi+lo), group with stage 0 ----
#pragma unroll
    for (int i = 0; i < 8; i++) {
        const int idx = tid + i * 256;     // 0..2047
        const int arr = idx >> 10;         // 0=Qh 1=Ql
        const int r   = (idx >> 3) & 127;
        const int seg = idx & 7;
        const uint32_t dst = sb + arr * AT_QBYTES + r * 128 + ((seg ^ (r & 7)) << 4);
        const __nv_bfloat16* src = (arr ? ql_g : qh_g) + (size_t)r * DKH + seg * 8;
        cp_async16(dst, src);
    }

    auto load_stage = [&](int kt, int s) {
        const int n0 = kt * BC;
        const uint32_t sbase = sb + 2 * AT_QBYTES + s * AT_STAGE;
#pragma unroll
        for (int i = 0; i < 8; i++) {
            const int idx = tid + i * 256;   // 0..2047
            const int arr = idx >> 9;        // 0 Kh, 1 Kl, 2 Vth, 3 Vtl
            const int r   = (idx >> 3) & 63;
            const int seg = idx & 7;
            const uint32_t dst = sbase + arr * 8192 + r * 128 + ((seg ^ (r & 7)) << 4);
            const __nv_bfloat16* src;
            if (arr == 0)      src = kh_g  + ((size_t)(n0 + r)) * DKH + seg * 8;
            else if (arr == 1) src = kl_g  + ((size_t)(n0 + r)) * DKH + seg * 8;
            else if (arr == 2) src = vth_g + (size_t)r * SQ + n0 + seg * 8;
            else               src = vtl_g + (size_t)r * SQ + n0 + seg * 8;
            cp_async16(dst, src);
        }
        CP_COMMIT();
    };

    load_stage(0, 0);   // group0 = Q + stage0
    load_stage(1, 1);   // group1 = stage1

    // state
    float Oacc[8][4];
#pragma unroll
    for (int j = 0; j < 8; j++)
#pragma unroll
        for (int f = 0; f < 4; f++) Oacc[j][f] = 0.f;
    float m0r = -1e30f, m1r = -1e30f, l0r = 0.f, l1r = 0.f;

    const int a_row  = wid * 16 + (lane & 15);
    const int a_kseg = lane >> 4;
    const int b_rowc = (lane & 7) | ((lane & 16) >> 1);
    const int b_kseg = (lane & 8) >> 3;

    for (int kt = 0; kt < NTK; kt++) {
        if (kt == NTK - 1) { CP_WAIT(0); } else { CP_WAIT(1); }
        __syncthreads();

        const uint32_t st  = sb + 2 * AT_QBYTES + (kt & 1) * AT_STAGE;
        const uint32_t sKh = st, sKl = st + 8192, sVh = st + 16384, sVl = st + 24576;

        // ---- S = Q K^T (3 terms) ----
        float S[8][4];
#pragma unroll
        for (int j = 0; j < 8; j++)
#pragma unroll
            for (int f = 0; f < 4; f++) S[j][f] = 0.f;

#pragma unroll
        for (int ks = 0; ks < 4; ks++) {
            uint32_t aqh[4], aql[4];
            {
                const uint32_t addr = sb + a_row * 128 +
                                      (((a_kseg + ks * 2) ^ (a_row & 7)) << 4);
                LDSM_X4(aqh[0], aqh[1], aqh[2], aqh[3], addr);
                const uint32_t addrl = addr + AT_QBYTES;
                LDSM_X4(aql[0], aql[1], aql[2], aql[3], addrl);
            }
#pragma unroll
            for (int j2 = 0; j2 < 4; j2++) {
                const int brow = j2 * 16 + b_rowc;
                const uint32_t ksw = (((b_kseg + ks * 2) ^ (brow & 7)) << 4);
                uint32_t bkh[4], bkl[4];
                LDSM_X4(bkh[0], bkh[1], bkh[2], bkh[3], sKh + brow * 128 + ksw);
                LDSM_X4(bkl[0], bkl[1], bkl[2], bkl[3], sKl + brow * 128 + ksw);
                MMA_BF16(S[j2*2][0], S[j2*2][1], S[j2*2][2], S[j2*2][3],
                         aqh[0], aqh[1], aqh[2], aqh[3], bkh[0], bkh[1]);
                MMA_BF16(S[j2*2+1][0], S[j2*2+1][1], S[j2*2+1][2], S[j2*2+1][3],
                         aqh[0], aqh[1], aqh[2], aqh[3], bkh[2], bkh[3]);
                MMA_BF16(S[j2*2][0], S[j2*2][1], S[j2*2][2], S[j2*2][3],
                         aql[0], aql[1], aql[2], aql[3], bkh[0], bkh[1]);
                MMA_BF16(S[j2*2+1][0], S[j2*2+1][1], S[j2*2+1][2], S[j2*2+1][3],
                         aql[0], aql[1], aql[2], aql[3], bkh[2], bkh[3]);
                MMA_BF16(S[j2*2][0], S[j2*2][1], S[j2*2][2], S[j2*2][3],
                         aqh[0], aqh[1], aqh[2], aqh[3], bkl[0], bkl[1]);
                MMA_BF16(S[j2*2+1][0], S[j2*2+1][1], S[j2*2+1][2], S[j2*2+1][3],
                         aqh[0], aqh[1], aqh[2], aqh[3], bkl[2], bkl[3]);
            }
        }

        // ---- online softmax ----
        float mx0 = -1e30f, mx1 = -1e30f;
#pragma unroll
        for (int j = 0; j < 8; j++) {
            mx0 = fmaxf(mx0, fmaxf(S[j][0], S[j][1]));
            mx1 = fmaxf(mx1, fmaxf(S[j][2], S[j][3]));
        }
        mx0 = fmaxf(mx0, __shfl_xor_sync(0xffffffffu, mx0, 1));
        mx0 = fmaxf(mx0, __shfl_xor_sync(0xffffffffu, mx0, 2));
        mx1 = fmaxf(mx1, __shfl_xor_sync(0xffffffffu, mx1, 1));
        mx1 = fmaxf(mx1, __shfl_xor_sync(0xffffffffu, mx1, 2));

        const float mn0 = fmaxf(m0r, mx0), mn1 = fmaxf(m1r, mx1);
        const float al0 = __expf(m0r - mn0), al1 = __expf(m1r - mn1);
        m0r = mn0; m1r = mn1;

        float ps0 = 0.f, ps1 = 0.f;
#pragma unroll
        for (int j = 0; j < 8; j++) {
            S[j][0] = __expf(S[j][0] - mn0); ps0 += S[j][0];
            S[j][1] = __expf(S[j][1] - mn0); ps0 += S[j][1];
            S[j][2] = __expf(S[j][2] - mn1); ps1 += S[j][2];
            S[j][3] = __expf(S[j][3] - mn1); ps1 += S[j][3];
        }
        l0r = l0r * al0 + ps0;
        l1r = l1r * al1 + ps1;
#pragma unroll
        for (int j = 0; j < 8; j++) {
            Oacc[j][0] *= al0; Oacc[j][1] *= al0;
            Oacc[j][2] *= al1; Oacc[j][3] *= al1;
        }

        // ---- P frags (hi) ----
        uint32_t aP[4][4];
#pragma unroll
        for (int t = 0; t < 4; t++) {
            aP[t][0] = pack_bf16(S[2*t][0],   S[2*t][1]);
            aP[t][1] = pack_bf16(S[2*t][2],   S[2*t][3]);
            aP[t][2] = pack_bf16(S[2*t+1][0], S[2*t+1][1]);
            aP[t][3] = pack_bf16(S[2*t+1][2], S[2*t+1][3]);
        }

        // ---- PV pass 1: ph*vh + ph*vl ----
#pragma unroll
        for (int t = 0; t < 4; t++) {
#pragma unroll
            for (int j2 = 0; j2 < 4; j2++) {
                const int brow = j2 * 16 + b_rowc;
                const uint32_t ksw = (((b_kseg + t * 2) ^ (brow & 7)) << 4);
                uint32_t bvh[4], bvl[4];
                LDSM_X4(bvh[0], bvh[1], bvh[2], bvh[3], sVh + brow * 128 + ksw);
                LDSM_X4(bvl[0], bvl[1], bvl[2], bvl[3], sVl + brow * 128 + ksw);
                MMA_BF16(Oacc[j2*2][0], Oacc[j2*2][1], Oacc[j2*2][2], Oacc[j2*2][3],
                         aP[t][0], aP[t][1], aP[t][2], aP[t][3], bvh[0], bvh[1]);
                MMA_BF16(Oacc[j2*2+1][0], Oacc[j2*2+1][1], Oacc[j2*2+1][2], Oacc[j2*2+1][3],
                         aP[t][0], aP[t][1], aP[t][2], aP[t][3], bvh[2], bvh[3]);
                MMA_BF16(Oacc[j2*2][0], Oacc[j2*2][1], Oacc[j2*2][2], Oacc[j2*2][3],
                         aP[t][0], aP[t][1], aP[t][2], aP[t][3], bvl[0], bvl[1]);
                MMA_BF16(Oacc[j2*2+1][0], Oacc[j2*2+1][1], Oacc[j2*2+1][2], Oacc[j2*2+1][3],
                         aP[t][0], aP[t][1], aP[t][2], aP[t][3], bvl[2], bvl[3]);
            }
        }

        // ---- P frags (lo) in place, then PV pass 2: pl*vh ----
#pragma unroll
        for (int t = 0; t < 4; t++) {
            float2 h0 = unpack_bf16(aP[t][0]);
            float2 h1 = unpack_bf16(aP[t][1]);
            float2 h2 = unpack_bf16(aP[t][2]);
            float2 h3 = unpack_bf16(aP[t][3]);
            aP[t][0] = pack_bf16(S[2*t][0]   - h0.x, S[2*t][1]   - h0.y);
            aP[t][1] = pack_bf16(S[2*t][2]   - h1.x, S[2*t][3]   - h1.y);
            aP[t][2] = pack_bf16(S[2*t+1][0] - h2.x, S[2*t+1][1] - h2.y);
            aP[t][3] = pack_bf16(S[2*t+1][2] - h3.x, S[2*t+1][3] - h3.y);
        }
#pragma unroll
        for (int t = 0; t < 4; t++) {
#pragma unroll
            for (int j2 = 0; j2 < 4; j2++) {
                const int brow = j2 * 16 + b_rowc;
                const uint32_t ksw = (((b_kseg + t * 2) ^ (brow & 7)) << 4);
                uint32_t bvh[4];
                LDSM_X4(bvh[0], bvh[1], bvh[2], bvh[3], sVh + brow * 128 + ksw);
                MMA_BF16(Oacc[j2*2][0], Oacc[j2*2][1], Oacc[j2*2][2], Oacc[j2*2][3],
                         aP[t][0], aP[t][1], aP[t][2], aP[t][3], bvh[0], bvh[1]);
                MMA_BF16(Oacc[j2*2+1][0], Oacc[j2*2+1][1], Oacc[j2*2+1][2], Oacc[j2*2+1][3],
                         aP[t][0], aP[t][1], aP[t][2], aP[t][3], bvh[2], bvh[3]);
            }
        }

        __syncthreads();   // done reading this stage
        if (kt + 2 < NTK) load_stage(kt + 2, kt & 1);
    }

    // ---- finalize ----
    l0r += __shfl_xor_sync(0xffffffffu, l0r, 1);
    l0r += __shfl_xor_sync(0xffffffffu, l0r, 2);
    l1r += __shfl_xor_sync(0xffffffffu, l1r, 1);
    l1r += __shfl_xor_sync(0xffffffffu, l1r, 2);
    const float inv0 = 1.f / l0r, inv1 = 1.f / l1r;

    const int r0 = lane >> 2;
    const size_t rowbase = (size_t)b * SQ + m0 + wid * 16;
#pragma unroll
    for (int j = 0; j < 8; j++) {
        const int d = (lane & 3) * 2 + j * 8;
        float2 v0 = make_float2(Oacc[j][0] * inv0, Oacc[j][1] * inv0);
        float2 v1 = make_float2(Oacc[j][2] * inv1, Oacc[j][3] * inv1);
        *reinterpret_cast<float2*>(&g_ctx[(rowbase + r0)     * DMODEL + h * DKH + d]) = v0;
        *reinterpret_cast<float2*>(&g_ctx[(rowbase + r0 + 8) * DMODEL + h * DKH + d]) = v1;
    }
}

// ---------------------------------------------------------------------------
extern "C" void kernel_launch(void* const* d_in, const int* in_sizes, int n_in,
                              void* d_out, int out_size)
{
    const float* q  = (const float*)d_in[0];
    const float* k  = (const float*)d_in[1];
    const float* v  = (const float*)d_in[2];
    const float* Wq = (const float*)d_in[3];
    const float* bq = (const float*)d_in[4];
    const float* Wk = (const float*)d_in[5];
    const float* bk = (const float*)d_in[6];
    const float* Wv = (const float*)d_in[7];
    const float* bv = (const float*)d_in[8];
    const float* Wo = (const float*)d_in[9];
    const float* bo = (const float*)d_in[10];
    float* out = (float*)d_out;

    float* gctx;
    __nv_bfloat16 *sA, *sB, *qh, *ql, *kh, *kl, *vth, *vtl;
    cudaGetSymbolAddress((void**)&gctx, g_ctx);
    cudaGetSymbolAddress((void**)&sA,   g_splitA);
    cudaGetSymbolAddress((void**)&sB,   g_splitB);
    cudaGetSymbolAddress((void**)&qh,   g_qh);
    cudaGetSymbolAddress((void**)&ql,   g_ql);
    cudaGetSymbolAddress((void**)&kh,   g_kh);
    cudaGetSymbolAddress((void**)&kl,   g_kl);
    cudaGetSymbolAddress((void**)&vth,  g_vth);
    cudaGetSymbolAddress((void**)&vtl,  g_vtl);

    cudaFuncSetAttribute(flash_hmma_kernel,
                         cudaFuncAttributeMaxDynamicSharedMemorySize, ATTN_SMEM);
    cudaFuncSetAttribute(gemm_tc_kernel<0>,
                         cudaFuncAttributeMaxDynamicSharedMemorySize, GEMM_SMEM);
    cudaFuncSetAttribute(gemm_tc_kernel<2>,
                         cudaFuncAttributeMaxDynamicSharedMemorySize, GEMM_SMEM);
    cudaFuncSetAttribute(gemm_tc_kernel<3>,
                         cudaFuncAttributeMaxDynamicSharedMemorySize, GEMM_SMEM);
    cudaFuncSetAttribute(gemm_tc_kernel<4>,
                         cudaFuncAttributeMaxDynamicSharedMemorySize, GEMM_SMEM);

    const dim3 gemm_grid(DMODEL / TN, MROWS / TM);         // (8, 32)
    const int  splitA_blocks = MROWS * DMODEL / 4 / 256;   // 4096
    const int  splitW_blocks = DMODEL * DMODEL / 4 / 256;  // 1024

    // Q projection -> split bf16 (scaled 1/8)
    split_kernel<0><<<splitA_blocks, 256>>>(q, sA);
    split_kernel<1><<<splitW_blocks, 256>>>(Wq, sB);
    gemm_tc_kernel<2><<<gemm_grid, 256, GEMM_SMEM>>>(sA, sB, bq, nullptr, qh, ql);
    // K projection
    split_kernel<0><<<splitA_blocks, 256>>>(k, sA);
    split_kernel<1><<<splitW_blocks, 256>>>(Wk, sB);
    gemm_tc_kernel<3><<<gemm_grid, 256, GEMM_SMEM>>>(sA, sB, bk, nullptr, kh, kl);
    // V projection (transposed split)
    split_kernel<0><<<splitA_blocks, 256>>>(v, sA);
    split_kernel<1><<<splitW_blocks, 256>>>(Wv, sB);
    gemm_tc_kernel<4><<<gemm_grid, 256, GEMM_SMEM>>>(sA, sB, bv, nullptr, vth, vtl);

    // attention (HMMA flash)
    dim3 attn_grid(SQ / BR, NH, BNC);    // (16, 16, 2)
    flash_hmma_kernel<<<attn_grid, 256, ATTN_SMEM>>>();

    // output projection
    split_kernel<0><<<splitA_blocks, 256>>>(gctx, sA);
    split_kernel<1><<<splitW_blocks, 256>>>(Wo, sB);
    gemm_tc_kernel<0><<<gemm_grid, 256, GEMM_SMEM>>>(sA, sB, bo, out, nullptr, nullptr);
}

// round 5
// speedup vs baseline: 3.1551x; 1.0812x over previous
#include <cuda_runtime.h>
#include <cuda_bf16.h>
#include <cstdint>

// Problem constants
#define BNC    2
#define SQ     2048
#define DMODEL 1024
#define NH     16
#define DKH    64
#define MROWS  (BNC * SQ)   // 4096
#define K2     (2 * DMODEL) // 2048 stored split width ([hi | lo])
#define NT     48           // virtual 3072-K in 64-elem chunks

// Scratch (device globals; no allocation allowed)
__device__ __nv_bfloat16 g_splitA[MROWS * K2];   // 16 MB
__device__ __nv_bfloat16 g_splitB[DMODEL * K2];  // 4 MB
__device__ __nv_bfloat16 g_qh[MROWS * DMODEL];   // [B,H,S,64], pre-scaled 1/8
__device__ __nv_bfloat16 g_ql[MROWS * DMODEL];
__device__ __nv_bfloat16 g_kh[MROWS * DMODEL];   // [B,H,S,64]
__device__ __nv_bfloat16 g_kl[MROWS * DMODEL];
__device__ __nv_bfloat16 g_vth[MROWS * DMODEL];  // [B,H,64,S] (V transposed)
__device__ __nv_bfloat16 g_vtl[MROWS * DMODEL];

// ============================================================================
// PTX helpers (compute_103-safe)
// ============================================================================
__device__ __forceinline__ uint32_t smem_u32(const void* p) {
    uint32_t a;
    asm("{ .reg .u64 t; cvta.to.shared.u64 t, %1; cvt.u32.u64 %0, t; }" : "=r"(a) : "l"(p));
    return a;
}
__device__ __forceinline__ void cp_async16(uint32_t dst, const void* src) {
    asm volatile("cp.async.cg.shared.global [%0], [%1], 16;" :: "r"(dst), "l"(src));
}
#define CP_COMMIT() asm volatile("cp.async.commit_group;" ::: "memory")
#define CP_WAIT(n)  asm volatile("cp.async.wait_group %0;" :: "n"(n) : "memory")

#define LDSM_X4(r0, r1, r2, r3, addr) \
    asm volatile("ldmatrix.sync.aligned.m8n8.x4.shared.b16 {%0,%1,%2,%3}, [%4];" \
                 : "=r"(r0), "=r"(r1), "=r"(r2), "=r"(r3) : "r"(addr))

#define MMA_BF16(c0, c1, c2, c3, a0, a1, a2, a3, b0, b1) \
    asm volatile("mma.sync.aligned.m16n8k16.row.col.f32.bf16.bf16.f32 " \
                 "{%0,%1,%2,%3}, {%4,%5,%6,%7}, {%8,%9}, {%0,%1,%2,%3};" \
                 : "+f"(c0), "+f"(c1), "+f"(c2), "+f"(c3) \
                 : "r"(a0), "r"(a1), "r"(a2), "r"(a3), "r"(b0), "r"(b1))

__device__ __forceinline__ uint32_t pack_bf16(float a, float b) {
    __nv_bfloat162 t = __float22bfloat162_rn(make_float2(a, b));
    return *reinterpret_cast<uint32_t*>(&t);
}
__device__ __forceinline__ float2 unpack_bf16(uint32_t r) {
    __nv_bfloat162 t = *reinterpret_cast<__nv_bfloat162*>(&r);
    return __bfloat1622float2(t);
}

// ============================================================================
// Split conversion: x[r,1024] -> dst[r, 2048] = [hi | lo]
// ============================================================================
__global__ __launch_bounds__(256)
void split_kernel(const float* __restrict__ src, __nv_bfloat16* __restrict__ dst)
{
    const int idx4 = blockIdx.x * 256 + threadIdx.x;
    const int r  = idx4 >> 8;
    const int k4 = (idx4 & 255) << 2;
    float4 x = *reinterpret_cast<const float4*>(&src[(size_t)r * DMODEL + k4]);

    __nv_bfloat16 h0 = __float2bfloat16(x.x), h1 = __float2bfloat16(x.y);
    __nv_bfloat16 h2 = __float2bfloat16(x.z), h3 = __float2bfloat16(x.w);
    __nv_bfloat16 l0 = __float2bfloat16(x.x - __bfloat162float(h0));
    __nv_bfloat16 l1 = __float2bfloat16(x.y - __bfloat162float(h1));
    __nv_bfloat16 l2 = __float2bfloat16(x.z - __bfloat162float(h2));
    __nv_bfloat16 l3 = __float2bfloat16(x.w - __bfloat162float(h3));

    const size_t base = (size_t)r * K2 + k4;
    __nv_bfloat162* p0 = reinterpret_cast<__nv_bfloat162*>(&dst[base]);
    __nv_bfloat162* p1 = reinterpret_cast<__nv_bfloat162*>(&dst[base + DMODEL]);
    p0[0] = __nv_bfloat162(h0, h1); p0[1] = __nv_bfloat162(h2, h3);
    p1[0] = __nv_bfloat162(l0, l1); p1[1] = __nv_bfloat162(l2, l3);
}

// ============================================================================
// HMMA GEMM with virtual 3-term K expansion:
//   A-term order: [hi | lo | hi]  -> offA(c) = (c<32 ? c : c-32)
//   B-term order: [hi | hi | lo]  -> offB(c) = (c<16 ? c : c-16)
// CTA 128x128, 8 warps (2x4), 3-stage cp.async, 2 CTAs/SM (one wave).
// MODE 0: fp32 [M,1024]   MODE 2: Q split (scale 1/8)  MODE 3: K split
// MODE 4: V split transposed
// ============================================================================
#define TM 128
#define TN 128
#define NS 3
#define STAGE_BYTES ((TM + TN) * 128) // 32768
#define GEMM_SMEM   (NS * STAGE_BYTES)

template <int MODE>
__global__ __launch_bounds__(256, 2)
void gemm_tc_kernel(const __nv_bfloat16* __restrict__ A,
                    const __nv_bfloat16* __restrict__ B,
                    const float* __restrict__ bias,
                    float* __restrict__ C,
                    __nv_bfloat16* __restrict__ OH,
                    __nv_bfloat16* __restrict__ OL)
{
    extern __shared__ __align__(1024) char smem[];
    const uint32_t sb = smem_u32(smem);
    const int tid  = threadIdx.x;
    const int wid  = tid >> 5;
    const int lane = tid & 31;
    const int wm   = wid >> 2;
    const int wn   = wid & 3;
    const int n0   = blockIdx.x * TN;
    const int m0   = blockIdx.y * TM;

    const char* Abase = reinterpret_cast<const char*>(A) + (size_t)m0 * (K2 * 2);
    const char* Bbase = reinterpret_cast<const char*>(B) + (size_t)n0 * (K2 * 2);

    auto load_chunk = [&](int c, int s) {
        const uint32_t st = sb + s * STAGE_BYTES;
        const int offA = ((c < 32) ? c : c - 32) * 128;
        const int offB = ((c < 16) ? c : c - 16) * 128;
#pragma unroll
        for (int i = 0; i < 8; i++) {
            const int idx = tid + i * 256;
            const int row = idx >> 3, seg = idx & 7;
            const uint32_t dst = st + row * 128 + ((seg ^ (row & 7)) << 4);
            const char* src = (row < TM)
                ? Abase + (size_t)row * (K2 * 2) + offA + seg * 16
                : Bbase + (size_t)(row - TM) * (K2 * 2) + offB + seg * 16;
            cp_async16(dst, src);
        }
        CP_COMMIT();
    };

    float acc[4][4][4];
#pragma unroll
    for (int i = 0; i < 4; i++)
#pragma unroll
        for (int j = 0; j < 4; j++)
#pragma unroll
            for (int f = 0; f < 4; f++) acc[i][j][f] = 0.f;

    load_chunk(0, 0);
    load_chunk(1, 1);

    const int a_row  = wm * 64 + (lane & 15);
    const int a_kseg = (lane >> 4);
    const int b_row  = wn * 32 + ((lane & 7) | ((lane & 16) >> 1));
    const int b_kseg = (lane & 8) >> 3;

    for (int kt = 0; kt < NT; kt++) {
        if (kt == NT - 1) { CP_WAIT(0); } else { CP_WAIT(1); }
        __syncthreads();

        const uint32_t st  = sb + (kt % NS) * STAGE_BYTES;
        const uint32_t sBm = st + TM * 128;

#pragma unroll
        for (int ks = 0; ks < 4; ks++) {
            uint32_t af[4][4];
#pragma unroll
            for (int i = 0; i < 4; i++) {
                const int row = a_row + i * 16;
                const uint32_t addr = st + row * 128 + (((a_kseg + ks * 2) ^ (row & 7)) << 4);
                LDSM_X4(af[i][0], af[i][1], af[i][2], af[i][3], addr);
            }
            uint32_t bf[2][4];
#pragma unroll
            for (int j2 = 0; j2 < 2; j2++) {
                const int brow = b_row + j2 * 16;
                const uint32_t baddr = sBm + brow * 128 + (((b_kseg + ks * 2) ^ (brow & 7)) << 4);
                LDSM_X4(bf[j2][0], bf[j2][1], bf[j2][2], bf[j2][3], baddr);
            }
#pragma unroll
            for (int i = 0; i < 4; i++) {
#pragma unroll
                for (int j2 = 0; j2 < 2; j2++) {
                    MMA_BF16(acc[i][j2 * 2 + 0][0], acc[i][j2 * 2 + 0][1],
                             acc[i][j2 * 2 + 0][2], acc[i][j2 * 2 + 0][3],
                             af[i][0], af[i][1], af[i][2], af[i][3],
                             bf[j2][0], bf[j2][1]);
                    MMA_BF16(acc[i][j2 * 2 + 1][0], acc[i][j2 * 2 + 1][1],
                             acc[i][j2 * 2 + 1][2], acc[i][j2 * 2 + 1][3],
                             af[i][0], af[i][1], af[i][2], af[i][3],
                             bf[j2][2], bf[j2][3]);
                }
            }
        }

        if (kt + NS - 1 < NT) load_chunk(kt + NS - 1, (kt + NS - 1) % NS);
    }

    const int crow = m0 + wm * 64 + (lane >> 2);
    const int ccol = n0 + wn * 32 + (lane & 3) * 2;
#pragma unroll
    for (int i = 0; i < 4; i++) {
#pragma unroll
        for (int j = 0; j < 4; j++) {
            const int col = ccol + j * 8;
            const float2 bv = *reinterpret_cast<const float2*>(&bias[col]);
#pragma unroll
            for (int rh = 0; rh < 2; rh++) {
                const int m = crow + i * 16 + rh * 8;
                float2 v;
                v.x = acc[i][j][rh * 2 + 0] + bv.x;
                v.y = acc[i][j][rh * 2 + 1] + bv.y;
                if (MODE == 0) {
                    *reinterpret_cast<float2*>(&C[(size_t)m * DMODEL + col]) = v;
                } else {
                    if (MODE == 2) { v.x *= 0.125f; v.y *= 0.125f; }
                    __nv_bfloat162 hi = __float22bfloat162_rn(v);
                    float2 hf = __bfloat1622float2(hi);
                    __nv_bfloat162 lo = __float22bfloat162_rn(
                        make_float2(v.x - hf.x, v.y - hf.y));
                    const int b = m >> 11, s = m & (SQ - 1);
                    const int h = col >> 6, d = col & (DKH - 1);
                    if (MODE == 4) {
                        const size_t t0 = (((size_t)(b * NH + h) * DKH + d) * SQ + s);
                        const size_t t1 = t0 + SQ;
                        OH[t0] = hi.x; OH[t1] = hi.y;
                        OL[t0] = lo.x; OL[t1] = lo.y;
                    } else {
                        const size_t a0 = (((size_t)(b * NH + h) * SQ + s) * DKH + d);
                        *reinterpret_cast<__nv_bfloat162*>(&OH[a0]) = hi;
                        *reinterpret_cast<__nv_bfloat162*>(&OL[a0]) = lo;
                    }
                }
            }
        }
    }
}

// ============================================================================
// Flash attention, HMMA bf16 3-term splits. Br=128, Bc=64, 2-stage cp.async.
// Epilogue writes split-bf16 ctx directly into g_splitA ([hi|lo], K2 wide).
// ============================================================================
#define BR 128
#define BC 64
#define NTK (SQ / BC)        // 32
#define AT_QBYTES   16384
#define AT_STAGE    32768
#define ATTN_SMEM   (2 * AT_QBYTES + 2 * AT_STAGE)   // 98304

__global__ __launch_bounds__(256, 2)
void flash_hmma_kernel()
{
    extern __shared__ __align__(1024) char smem[];
    const uint32_t sb = smem_u32(smem);
    const int tid  = threadIdx.x;
    const int wid  = tid >> 5;
    const int lane = tid & 31;

    const int m0 = blockIdx.x * BR;
    const int h  = blockIdx.y;
    const int b  = blockIdx.z;
    const int bh = b * NH + h;

    const __nv_bfloat16* qh_g  = g_qh  + ((size_t)bh * SQ + m0) * DKH;
    const __nv_bfloat16* ql_g  = g_ql  + ((size_t)bh * SQ + m0) * DKH;
    const __nv_bfloat16* kh_g  = g_kh  + (size_t)bh * SQ * DKH;
    const __nv_bfloat16* kl_g  = g_kl  + (size_t)bh * SQ * DKH;
    const __nv_bfloat16* vth_g = g_vth + (size_t)bh * DKH * SQ;
    const __nv_bfloat16* vtl_g = g_vtl + (size_t)bh * DKH * SQ;

#pragma unroll
    for (int i = 0; i < 8; i++) {
        const int idx = tid + i * 256;
        const int arr = idx >> 10;
        const int r   = (idx >> 3) & 127;
        const int seg = idx & 7;
        const uint32_t dst = sb + arr * AT_QBYTES + r * 128 + ((seg ^ (r & 7)) << 4);
        const __nv_bfloat16* src = (arr ? ql_g : qh_g) + (size_t)r * DKH + seg * 8;
        cp_async16(dst, src);
    }

    auto load_stage = [&](int kt, int s) {
        const int n0 = kt * BC;
        const uint32_t sbase = sb + 2 * AT_QBYTES + s * AT_STAGE;
#pragma unroll
        for (int i = 0; i < 8; i++) {
            const int idx = tid + i * 256;
            const int arr = idx >> 9;
            const int r   = (idx >> 3) & 63;
            const int seg = idx & 7;
            const uint32_t dst = sbase + arr * 8192 + r * 128 + ((seg ^ (r & 7)) << 4);
            const __nv_bfloat16* src;
            if (arr == 0)      src = kh_g  + ((size_t)(n0 + r)) * DKH + seg * 8;
            else if (arr == 1) src = kl_g  + ((size_t)(n0 + r)) * DKH + seg * 8;
            else if (arr == 2) src = vth_g + (size_t)r * SQ + n0 + seg * 8;
            else               src = vtl_g + (size_t)r * SQ + n0 + seg * 8;
            cp_async16(dst, src);
        }
        CP_COMMIT();
    };

    load_stage(0, 0);
    load_stage(1, 1);

    float Oacc[8][4];
#pragma unroll
    for (int j = 0; j < 8; j++)
#pragma unroll
        for (int f = 0; f < 4; f++) Oacc[j][f] = 0.f;
    float m0r = -1e30f, m1r = -1e30f, l0r = 0.f, l1r = 0.f;

    const int a_row  = wid * 16 + (lane & 15);
    const int a_kseg = lane >> 4;
    const int b_rowc = (lane & 7) | ((lane & 16) >> 1);
    const int b_kseg = (lane & 8) >> 3;

    for (int kt = 0; kt < NTK; kt++) {
        if (kt == NTK - 1) { CP_WAIT(0); } else { CP_WAIT(1); }
        __syncthreads();

        const uint32_t st  = sb + 2 * AT_QBYTES + (kt & 1) * AT_STAGE;
        const uint32_t sKh = st, sKl = st + 8192, sVh = st + 16384, sVl = st + 24576;

        float S[8][4];
#pragma unroll
        for (int j = 0; j < 8; j++)
#pragma unroll
            for (int f = 0; f < 4; f++) S[j][f] = 0.f;

#pragma unroll
        for (int ks = 0; ks < 4; ks++) {
            uint32_t aqh[4], aql[4];
            {
                const uint32_t addr = sb + a_row * 128 +
                                      (((a_kseg + ks * 2) ^ (a_row & 7)) << 4);
                LDSM_X4(aqh[0], aqh[1], aqh[2], aqh[3], addr);
                const uint32_t addrl = addr + AT_QBYTES;
                LDSM_X4(aql[0], aql[1], aql[2], aql[3], addrl);
            }
#pragma unroll
            for (int j2 = 0; j2 < 4; j2++) {
                const int brow = j2 * 16 + b_rowc;
                const uint32_t ksw = (((b_kseg + ks * 2) ^ (brow & 7)) << 4);
                uint32_t bkh[4], bkl[4];
                LDSM_X4(bkh[0], bkh[1], bkh[2], bkh[3], sKh + brow * 128 + ksw);
                LDSM_X4(bkl[0], bkl[1], bkl[2], bkl[3], sKl + brow * 128 + ksw);
                MMA_BF16(S[j2*2][0], S[j2*2][1], S[j2*2][2], S[j2*2][3],
                         aqh[0], aqh[1], aqh[2], aqh[3], bkh[0], bkh[1]);
                MMA_BF16(S[j2*2+1][0], S[j2*2+1][1], S[j2*2+1][2], S[j2*2+1][3],
                         aqh[0], aqh[1], aqh[2], aqh[3], bkh[2], bkh[3]);
                MMA_BF16(S[j2*2][0], S[j2*2][1], S[j2*2][2], S[j2*2][3],
                         aql[0], aql[1], aql[2], aql[3], bkh[0], bkh[1]);
                MMA_BF16(S[j2*2+1][0], S[j2*2+1][1], S[j2*2+1][2], S[j2*2+1][3],
                         aql[0], aql[1], aql[2], aql[3], bkh[2], bkh[3]);
                MMA_BF16(S[j2*2][0], S[j2*2][1], S[j2*2][2], S[j2*2][3],
                         aqh[0], aqh[1], aqh[2], aqh[3], bkl[0], bkl[1]);
                MMA_BF16(S[j2*2+1][0], S[j2*2+1][1], S[j2*2+1][2], S[j2*2+1][3],
                         aqh[0], aqh[1], aqh[2], aqh[3], bkl[2], bkl[3]);
            }
        }

        float mx0 = -1e30f, mx1 = -1e30f;
#pragma unroll
        for (int j = 0; j < 8; j++) {
            mx0 = fmaxf(mx0, fmaxf(S[j][0], S[j][1]));
            mx1 = fmaxf(mx1, fmaxf(S[j][2], S[j][3]));
        }
        mx0 = fmaxf(mx0, __shfl_xor_sync(0xffffffffu, mx0, 1));
        mx0 = fmaxf(mx0, __shfl_xor_sync(0xffffffffu, mx0, 2));
        mx1 = fmaxf(mx1, __shfl_xor_sync(0xffffffffu, mx1, 1));
        mx1 = fmaxf(mx1, __shfl_xor_sync(0xffffffffu, mx1, 2));

        const float mn0 = fmaxf(m0r, mx0), mn1 = fmaxf(m1r, mx1);
        const float al0 = __expf(m0r - mn0), al1 = __expf(m1r - mn1);
        m0r = mn0; m1r = mn1;

        float ps0 = 0.f, ps1 = 0.f;
#pragma unroll
        for (int j = 0; j < 8; j++) {
            S[j][0] = __expf(S[j][0] - mn0); ps0 += S[j][0];
            S[j][1] = __expf(S[j][1] - mn0); ps0 += S[j][1];
            S[j][2] = __expf(S[j][2] - mn1); ps1 += S[j][2];
            S[j][3] = __expf(S[j][3] - mn1); ps1 += S[j][3];
        }
        l0r = l0r * al0 + ps0;
        l1r = l1r * al1 + ps1;
#pragma unroll
        for (int j = 0; j < 8; j++) {
            Oacc[j][0] *= al0; Oacc[j][1] *= al0;
            Oacc[j][2] *= al1; Oacc[j][3] *= al1;
        }

        uint32_t aP[4][4];
#pragma unroll
        for (int t = 0; t < 4; t++) {
            aP[t][0] = pack_bf16(S[2*t][0],   S[2*t][1]);
            aP[t][1] = pack_bf16(S[2*t][2],   S[2*t][3]);
            aP[t][2] = pack_bf16(S[2*t+1][0], S[2*t+1][1]);
            aP[t][3] = pack_bf16(S[2*t+1][2], S[2*t+1][3]);
        }

#pragma unroll
        for (int t = 0; t < 4; t++) {
#pragma unroll
            for (int j2 = 0; j2 < 4; j2++) {
                const int brow = j2 * 16 + b_rowc;
                const uint32_t ksw = (((b_kseg + t * 2) ^ (brow & 7)) << 4);
                uint32_t bvh[4], bvl[4];
                LDSM_X4(bvh[0], bvh[1], bvh[2], bvh[3], sVh + brow * 128 + ksw);
                LDSM_X4(bvl[0], bvl[1], bvl[2], bvl[3], sVl + brow * 128 + ksw);
                MMA_BF16(Oacc[j2*2][0], Oacc[j2*2][1], Oacc[j2*2][2], Oacc[j2*2][3],
                         aP[t][0], aP[t][1], aP[t][2], aP[t][3], bvh[0], bvh[1]);
                MMA_BF16(Oacc[j2*2+1][0], Oacc[j2*2+1][1], Oacc[j2*2+1][2], Oacc[j2*2+1][3],
                         aP[t][0], aP[t][1], aP[t][2], aP[t][3], bvh[2], bvh[3]);
                MMA_BF16(Oacc[j2*2][0], Oacc[j2*2][1], Oacc[j2*2][2], Oacc[j2*2][3],
                         aP[t][0], aP[t][1], aP[t][2], aP[t][3], bvl[0], bvl[1]);
                MMA_BF16(Oacc[j2*2+1][0], Oacc[j2*2+1][1], Oacc[j2*2+1][2], Oacc[j2*2+1][3],
                         aP[t][0], aP[t][1], aP[t][2], aP[t][3], bvl[2], bvl[3]);
            }
        }

#pragma unroll
        for (int t = 0; t < 4; t++) {
            float2 h0 = unpack_bf16(aP[t][0]);
            float2 h1 = unpack_bf16(aP[t][1]);
            float2 h2 = unpack_bf16(aP[t][2]);
            float2 h3 = unpack_bf16(aP[t][3]);
            aP[t][0] = pack_bf16(S[2*t][0]   - h0.x, S[2*t][1]   - h0.y);
            aP[t][1] = pack_bf16(S[2*t][2]   - h1.x, S[2*t][3]   - h1.y);
            aP[t][2] = pack_bf16(S[2*t+1][0] - h2.x, S[2*t+1][1] - h2.y);
            aP[t][3] = pack_bf16(S[2*t+1][2] - h3.x, S[2*t+1][3] - h3.y);
        }
#pragma unroll
        for (int t = 0; t < 4; t++) {
#pragma unroll
            for (int j2 = 0; j2 < 4; j2++) {
                const int brow = j2 * 16 + b_rowc;
                const uint32_t ksw = (((b_kseg + t * 2) ^ (brow & 7)) << 4);
                uint32_t bvh[4];
                LDSM_X4(bvh[0], bvh[1], bvh[2], bvh[3], sVh + brow * 128 + ksw);
                MMA_BF16(Oacc[j2*2][0], Oacc[j2*2][1], Oacc[j2*2][2], Oacc[j2*2][3],
                         aP[t][0], aP[t][1], aP[t][2], aP[t][3], bvh[0], bvh[1]);
                MMA_BF16(Oacc[j2*2+1][0], Oacc[j2*2+1][1], Oacc[j2*2+1][2], Oacc[j2*2+1][3],
                         aP[t][0], aP[t][1], aP[t][2], aP[t][3], bvh[2], bvh[3]);
            }
        }

        __syncthreads();
        if (kt + 2 < NTK) load_stage(kt + 2, kt & 1);
    }

    // finalize: write split-bf16 ctx directly into g_splitA ([hi|lo], K2 wide)
    l0r += __shfl_xor_sync(0xffffffffu, l0r, 1);
    l0r += __shfl_xor_sync(0xffffffffu, l0r, 2);
    l1r += __shfl_xor_sync(0xffffffffu, l1r, 1);
    l1r += __shfl_xor_sync(0xffffffffu, l1r, 2);
    const float inv0 = 1.f / l0r, inv1 = 1.f / l1r;

    const int r0 = lane >> 2;
    const size_t rowbase = (size_t)b * SQ + m0 + wid * 16;
#pragma unroll
    for (int j = 0; j < 8; j++) {
        const int col = h * DKH + (lane & 3) * 2 + j * 8;
#pragma unroll
        for (int rh = 0; rh < 2; rh++) {
            float2 v = (rh == 0)
                ? make_float2(Oacc[j][0] * inv0, Oacc[j][1] * inv0)
                : make_float2(Oacc[j][2] * inv1, Oacc[j][3] * inv1);
            __nv_bfloat162 hi = __float22bfloat162_rn(v);
            float2 hf = __bfloat1622float2(hi);
            __nv_bfloat162 lo = __float22bfloat162_rn(make_float2(v.x - hf.x, v.y - hf.y));
            const size_t m = rowbase + r0 + rh * 8;
            *reinterpret_cast<__nv_bfloat162*>(&g_splitA[m * K2 + col])          = hi;
            *reinterpret_cast<__nv_bfloat162*>(&g_splitA[m * K2 + DMODEL + col]) = lo;
        }
    }
}

// ---------------------------------------------------------------------------
extern "C" void kernel_launch(void* const* d_in, const int* in_sizes, int n_in,
                              void* d_out, int out_size)
{
    const float* q  = (const float*)d_in[0];
    const float* k  = (const float*)d_in[1];
    const float* v  = (const float*)d_in[2];
    const float* Wq = (const float*)d_in[3];
    const float* bq = (const float*)d_in[4];
    const float* Wk = (const float*)d_in[5];
    const float* bk = (const float*)d_in[6];
    const float* Wv = (const float*)d_in[7];
    const float* bv = (const float*)d_in[8];
    const float* Wo = (const float*)d_in[9];
    const float* bo = (const float*)d_in[10];
    float* out = (float*)d_out;

    __nv_bfloat16 *sA, *sB, *qh, *ql, *kh, *kl, *vth, *vtl;
    cudaGetSymbolAddress((void**)&sA,  g_splitA);
    cudaGetSymbolAddress((void**)&sB,  g_splitB);
    cudaGetSymbolAddress((void**)&qh,  g_qh);
    cudaGetSymbolAddress((void**)&ql,  g_ql);
    cudaGetSymbolAddress((void**)&kh,  g_kh);
    cudaGetSymbolAddress((void**)&kl,  g_kl);
    cudaGetSymbolAddress((void**)&vth, g_vth);
    cudaGetSymbolAddress((void**)&vtl, g_vtl);

    cudaFuncSetAttribute(flash_hmma_kernel,
                         cudaFuncAttributeMaxDynamicSharedMemorySize, ATTN_SMEM);
    cudaFuncSetAttribute(gemm_tc_kernel<0>,
                         cudaFuncAttributeMaxDynamicSharedMemorySize, GEMM_SMEM);
    cudaFuncSetAttribute(gemm_tc_kernel<2>,
                         cudaFuncAttributeMaxDynamicSharedMemorySize, GEMM_SMEM);
    cudaFuncSetAttribute(gemm_tc_kernel<3>,
                         cudaFuncAttributeMaxDynamicSharedMemorySize, GEMM_SMEM);
    cudaFuncSetAttribute(gemm_tc_kernel<4>,
                         cudaFuncAttributeMaxDynamicSharedMemorySize, GEMM_SMEM);

    const dim3 gemm_grid(DMODEL / TN, MROWS / TM);         // (8, 32)
    const int  splitA_blocks = MROWS * DMODEL / 4 / 256;   // 4096
    const int  splitW_blocks = DMODEL * DMODEL / 4 / 256;  // 1024

    // Q projection -> split bf16 (scaled 1/8)
    split_kernel<<<splitA_blocks, 256>>>(q, sA);
    split_kernel<<<splitW_blocks, 256>>>(Wq, sB);
    gemm_tc_kernel<2><<<gemm_grid, 256, GEMM_SMEM>>>(sA, sB, bq, nullptr, qh, ql);
    // K projection
    split_kernel<<<splitA_blocks, 256>>>(k, sA);
    split_kernel<<<splitW_blocks, 256>>>(Wk, sB);
    gemm_tc_kernel<3><<<gemm_grid, 256, GEMM_SMEM>>>(sA, sB, bk, nullptr, kh, kl);
    // V projection (transposed split)
    split_kernel<<<splitA_blocks, 256>>>(v, sA);
    split_kernel<<<splitW_blocks, 256>>>(Wv, sB);
    gemm_tc_kernel<4><<<gemm_grid, 256, GEMM_SMEM>>>(sA, sB, bv, nullptr, vth, vtl);

    // attention (writes split ctx into g_splitA)
    dim3 attn_grid(SQ / BR, NH, BNC);    // (16, 16, 2)
    flash_hmma_kernel<<<attn_grid, 256, ATTN_SMEM>>>();

    // output projection (reads split ctx from g_splitA)
    split_kernel<<<splitW_blocks, 256>>>(Wo, sB);
    gemm_tc_kernel<0><<<gemm_grid, 256, GEMM_SMEM>>>(sA, sB, bo, out, nullptr, nullptr);
}

// round 6
// speedup vs baseline: 3.2348x; 1.0252x over previous
#include <cuda_runtime.h>
#include <cuda_bf16.h>
#include <cstdint>

// Problem constants
#define BNC    2
#define SQ     2048
#define DMODEL 1024
#define NH     16
#define DKH    64
#define MROWS  (BNC * SQ)   // 4096
#define K2     (2 * DMODEL) // 2048 stored split width ([hi | lo])
#define NT     48           // virtual 3072-K in 64-elem chunks

// Scratch (device globals; no allocation allowed)
__device__ __nv_bfloat16 g_splitA[3 * MROWS * K2];   // 48 MB (3 slabs; slab0 reused for ctx)
__device__ __nv_bfloat16 g_splitB[4 * DMODEL * K2];  // 16 MB (Wq,Wk,Wv,Wo)
__device__ __nv_bfloat16 g_qh[MROWS * DMODEL];       // [B,H,S,64], pre-scaled 1/8
__device__ __nv_bfloat16 g_ql[MROWS * DMODEL];
__device__ __nv_bfloat16 g_kh[MROWS * DMODEL];       // [B,H,S,64]
__device__ __nv_bfloat16 g_kl[MROWS * DMODEL];
__device__ __nv_bfloat16 g_vth[MROWS * DMODEL];      // [B,H,64,S] (V transposed)
__device__ __nv_bfloat16 g_vtl[MROWS * DMODEL];

// ============================================================================
// PTX helpers (compute_103-safe)
// ============================================================================
__device__ __forceinline__ uint32_t smem_u32(const void* p) {
    uint32_t a;
    asm("{ .reg .u64 t; cvta.to.shared.u64 t, %1; cvt.u32.u64 %0, t; }" : "=r"(a) : "l"(p));
    return a;
}
__device__ __forceinline__ void cp_async16(uint32_t dst, const void* src) {
    asm volatile("cp.async.cg.shared.global [%0], [%1], 16;" :: "r"(dst), "l"(src));
}
#define CP_COMMIT() asm volatile("cp.async.commit_group;" ::: "memory")
#define CP_WAIT(n)  asm volatile("cp.async.wait_group %0;" :: "n"(n) : "memory")

#define LDSM_X4(r0, r1, r2, r3, addr) \
    asm volatile("ldmatrix.sync.aligned.m8n8.x4.shared.b16 {%0,%1,%2,%3}, [%4];" \
                 : "=r"(r0), "=r"(r1), "=r"(r2), "=r"(r3) : "r"(addr))

#define MMA_BF16(c0, c1, c2, c3, a0, a1, a2, a3, b0, b1) \
    asm volatile("mma.sync.aligned.m16n8k16.row.col.f32.bf16.bf16.f32 " \
                 "{%0,%1,%2,%3}, {%4,%5,%6,%7}, {%8,%9}, {%0,%1,%2,%3};" \
                 : "+f"(c0), "+f"(c1), "+f"(c2), "+f"(c3) \
                 : "r"(a0), "r"(a1), "r"(a2), "r"(a3), "r"(b0), "r"(b1))

__device__ __forceinline__ uint32_t pack_bf16(float a, float b) {
    __nv_bfloat162 t = __float22bfloat162_rn(make_float2(a, b));
    return *reinterpret_cast<uint32_t*>(&t);
}
__device__ __forceinline__ float2 unpack_bf16(uint32_t r) {
    __nv_bfloat162 t = *reinterpret_cast<__nv_bfloat162*>(&r);
    return __bfloat1622float2(t);
}

// ============================================================================
// Fused split kernels: x[r,1024] -> dst[r, 2048] = [hi | lo]
// ============================================================================
__device__ __forceinline__ void split_row4(const float* __restrict__ src,
                                           __nv_bfloat16* __restrict__ dst,
                                           int idx4)
{
    const int r  = idx4 >> 8;
    const int k4 = (idx4 & 255) << 2;
    float4 x = *reinterpret_cast<const float4*>(&src[(size_t)r * DMODEL + k4]);

    __nv_bfloat16 h0 = __float2bfloat16(x.x), h1 = __float2bfloat16(x.y);
    __nv_bfloat16 h2 = __float2bfloat16(x.z), h3 = __float2bfloat16(x.w);
    __nv_bfloat16 l0 = __float2bfloat16(x.x - __bfloat162float(h0));
    __nv_bfloat16 l1 = __float2bfloat16(x.y - __bfloat162float(h1));
    __nv_bfloat16 l2 = __float2bfloat16(x.z - __bfloat162float(h2));
    __nv_bfloat16 l3 = __float2bfloat16(x.w - __bfloat162float(h3));

    const size_t base = (size_t)r * K2 + k4;
    __nv_bfloat162* p0 = reinterpret_cast<__nv_bfloat162*>(&dst[base]);
    __nv_bfloat162* p1 = reinterpret_cast<__nv_bfloat162*>(&dst[base + DMODEL]);
    p0[0] = __nv_bfloat162(h0, h1); p0[1] = __nv_bfloat162(h2, h3);
    p1[0] = __nv_bfloat162(l0, l1); p1[1] = __nv_bfloat162(l2, l3);
}

// All three inputs in one launch: 3 x 4096 blocks
__global__ __launch_bounds__(256)
void split_qkv_kernel(const float* __restrict__ q, const float* __restrict__ k,
                      const float* __restrict__ v)
{
    const int which = blockIdx.x >> 12;          // 4096 blocks per tensor
    const int blk   = blockIdx.x & 4095;
    const float* src = (which == 0) ? q : (which == 1) ? k : v;
    __nv_bfloat16* dst = g_splitA + (size_t)which * MROWS * K2;
    split_row4(src, dst, blk * 256 + threadIdx.x);
}

// All four weights in one launch: 4 x 1024 blocks
__global__ __launch_bounds__(256)
void split_w_kernel(const float* __restrict__ wq, const float* __restrict__ wk,
                    const float* __restrict__ wv, const float* __restrict__ wo)
{
    const int which = blockIdx.x >> 10;          // 1024 blocks per tensor
    const int blk   = blockIdx.x & 1023;
    const float* src = (which == 0) ? wq : (which == 1) ? wk
                     : (which == 2) ? wv : wo;
    __nv_bfloat16* dst = g_splitB + (size_t)which * DMODEL * K2;
    split_row4(src, dst, blk * 256 + threadIdx.x);
}

// ============================================================================
// HMMA GEMM with virtual 3-term K expansion:
//   A-term order: [hi | lo | hi]  -> offA(c) = (c<32 ? c : c-32)
//   B-term order: [hi | hi | lo]  -> offB(c) = (c<16 ? c : c-16)
// CTA 128x128, 8 warps (2x4), 3-stage cp.async, 2 CTAs/SM.
// MODE 0: fp32 [M,1024] out (output projection; A slab0, B slab3)
// MODE 1: batched QKV (blockIdx.z = 0/1/2 -> Q/K/V epilogues)
// ============================================================================
#define TM 128
#define TN 128
#define NS 3
#define STAGE_BYTES ((TM + TN) * 128) // 32768
#define GEMM_SMEM   (NS * STAGE_BYTES)

template <int MODE>
__global__ __launch_bounds__(256, 2)
void gemm_tc_kernel(const float* __restrict__ bias0,
                    const float* __restrict__ bias1,
                    const float* __restrict__ bias2,
                    float* __restrict__ C)
{
    extern __shared__ __align__(1024) char smem[];
    const uint32_t sb = smem_u32(smem);
    const int tid  = threadIdx.x;
    const int wid  = tid >> 5;
    const int lane = tid & 31;
    const int wm   = wid >> 2;
    const int wn   = wid & 3;
    const int n0   = blockIdx.x * TN;
    const int m0   = blockIdx.y * TM;
    const int z    = (MODE == 1) ? blockIdx.z : 0;

    const __nv_bfloat16* A = (MODE == 1) ? (g_splitA + (size_t)z * MROWS * K2)
                                         : g_splitA;            // ctx in slab0
    const __nv_bfloat16* B = (MODE == 1) ? (g_splitB + (size_t)z * DMODEL * K2)
                                         : (g_splitB + (size_t)3 * DMODEL * K2);
    const float* bias = (MODE == 1)
        ? ((z == 0) ? bias0 : (z == 1) ? bias1 : bias2)
        : bias0;

    const char* Abase = reinterpret_cast<const char*>(A) + (size_t)m0 * (K2 * 2);
    const char* Bbase = reinterpret_cast<const char*>(B) + (size_t)n0 * (K2 * 2);

    auto load_chunk = [&](int c, int s) {
        const uint32_t st = sb + s * STAGE_BYTES;
        const int offA = ((c < 32) ? c : c - 32) * 128;
        const int offB = ((c < 16) ? c : c - 16) * 128;
#pragma unroll
        for (int i = 0; i < 8; i++) {
            const int idx = tid + i * 256;
            const int row = idx >> 3, seg = idx & 7;
            const uint32_t dst = st + row * 128 + ((seg ^ (row & 7)) << 4);
            const char* src = (row < TM)
                ? Abase + (size_t)row * (K2 * 2) + offA + seg * 16
                : Bbase + (size_t)(row - TM) * (K2 * 2) + offB + seg * 16;
            cp_async16(dst, src);
        }
        CP_COMMIT();
    };

    float acc[4][4][4];
#pragma unroll
    for (int i = 0; i < 4; i++)
#pragma unroll
        for (int j = 0; j < 4; j++)
#pragma unroll
            for (int f = 0; f < 4; f++) acc[i][j][f] = 0.f;

    load_chunk(0, 0);
    load_chunk(1, 1);

    const int a_row  = wm * 64 + (lane & 15);
    const int a_kseg = (lane >> 4);
    const int b_row  = wn * 32 + ((lane & 7) | ((lane & 16) >> 1));
    const int b_kseg = (lane & 8) >> 3;

    for (int kt = 0; kt < NT; kt++) {
        if (kt == NT - 1) { CP_WAIT(0); } else { CP_WAIT(1); }
        __syncthreads();

        const uint32_t st  = sb + (kt % NS) * STAGE_BYTES;
        const uint32_t sBm = st + TM * 128;

#pragma unroll
        for (int ks = 0; ks < 4; ks++) {
            uint32_t af[4][4];
#pragma unroll
            for (int i = 0; i < 4; i++) {
                const int row = a_row + i * 16;
                const uint32_t addr = st + row * 128 + (((a_kseg + ks * 2) ^ (row & 7)) << 4);
                LDSM_X4(af[i][0], af[i][1], af[i][2], af[i][3], addr);
            }
            uint32_t bf[2][4];
#pragma unroll
            for (int j2 = 0; j2 < 2; j2++) {
                const int brow = b_row + j2 * 16;
                const uint32_t baddr = sBm + brow * 128 + (((b_kseg + ks * 2) ^ (brow & 7)) << 4);
                LDSM_X4(bf[j2][0], bf[j2][1], bf[j2][2], bf[j2][3], baddr);
            }
#pragma unroll
            for (int i = 0; i < 4; i++) {
#pragma unroll
                for (int j2 = 0; j2 < 2; j2++) {
                    MMA_BF16(acc[i][j2 * 2 + 0][0], acc[i][j2 * 2 + 0][1],
                             acc[i][j2 * 2 + 0][2], acc[i][j2 * 2 + 0][3],
                             af[i][0], af[i][1], af[i][2], af[i][3],
                             bf[j2][0], bf[j2][1]);
                    MMA_BF16(acc[i][j2 * 2 + 1][0], acc[i][j2 * 2 + 1][1],
                             acc[i][j2 * 2 + 1][2], acc[i][j2 * 2 + 1][3],
                             af[i][0], af[i][1], af[i][2], af[i][3],
                             bf[j2][2], bf[j2][3]);
                }
            }
        }

        if (kt + NS - 1 < NT) load_chunk(kt + NS - 1, (kt + NS - 1) % NS);
    }

    const int crow = m0 + wm * 64 + (lane >> 2);
    const int ccol = n0 + wn * 32 + (lane & 3) * 2;
#pragma unroll
    for (int i = 0; i < 4; i++) {
#pragma unroll
        for (int j = 0; j < 4; j++) {
            const int col = ccol + j * 8;
            const float2 bv = *reinterpret_cast<const float2*>(&bias[col]);
#pragma unroll
            for (int rh = 0; rh < 2; rh++) {
                const int m = crow + i * 16 + rh * 8;
                float2 v;
                v.x = acc[i][j][rh * 2 + 0] + bv.x;
                v.y = acc[i][j][rh * 2 + 1] + bv.y;
                if (MODE == 0) {
                    *reinterpret_cast<float2*>(&C[(size_t)m * DMODEL + col]) = v;
                } else {
                    if (z == 0) { v.x *= 0.125f; v.y *= 0.125f; }
                    __nv_bfloat162 hi = __float22bfloat162_rn(v);
                    float2 hf = __bfloat1622float2(hi);
                    __nv_bfloat162 lo = __float22bfloat162_rn(
                        make_float2(v.x - hf.x, v.y - hf.y));
                    const int b = m >> 11, s = m & (SQ - 1);
                    const int h = col >> 6, d = col & (DKH - 1);
                    if (z == 2) {
                        const size_t t0 = (((size_t)(b * NH + h) * DKH + d) * SQ + s);
                        const size_t t1 = t0 + SQ;
                        g_vth[t0] = hi.x; g_vth[t1] = hi.y;
                        g_vtl[t0] = lo.x; g_vtl[t1] = lo.y;
                    } else {
                        const size_t a0 = (((size_t)(b * NH + h) * SQ + s) * DKH + d);
                        if (z == 0) {
                            *reinterpret_cast<__nv_bfloat162*>(&g_qh[a0]) = hi;
                            *reinterpret_cast<__nv_bfloat162*>(&g_ql[a0]) = lo;
                        } else {
                            *reinterpret_cast<__nv_bfloat162*>(&g_kh[a0]) = hi;
                            *reinterpret_cast<__nv_bfloat162*>(&g_kl[a0]) = lo;
                        }
                    }
                }
            }
        }
    }
}

// ============================================================================
// Persistent flash attention, HMMA bf16 3-term splits. Br=128, Bc=64.
// Grid = 296 CTAs (one full wave at 2 CTA/SM); static stride over 512 tiles.
// Single-pass PV with P-hi and P-lo fragments both live.
// Writes split-bf16 ctx into g_splitA slab 0.
// ============================================================================
#define BR 128
#define BC 64
#define NTK (SQ / BC)        // 32
#define NTILES 512           // 16 m-tiles x 16 heads x 2 batch
#define PGRID  296           // 148 SMs x 2 CTAs
#define AT_QBYTES   16384
#define AT_STAGE    32768
#define ATTN_SMEM   (2 * AT_QBYTES + 2 * AT_STAGE)   // 98304

__global__ __launch_bounds__(256, 2)
void flash_hmma_kernel()
{
    extern __shared__ __align__(1024) char smem[];
    const uint32_t sb = smem_u32(smem);
    const int tid  = threadIdx.x;
    const int wid  = tid >> 5;
    const int lane = tid & 31;

    const int a_row  = wid * 16 + (lane & 15);
    const int a_kseg = lane >> 4;
    const int b_rowc = (lane & 7) | ((lane & 16) >> 1);
    const int b_kseg = (lane & 8) >> 3;

    for (int tile = blockIdx.x; tile < NTILES; tile += PGRID) {
        const int m0 = (tile & 15) * BR;
        const int bh = tile >> 4;          // b*NH + h
        const int h  = bh & (NH - 1);
        const int b  = bh >> 4;

        const __nv_bfloat16* qh_g  = g_qh  + ((size_t)bh * SQ + m0) * DKH;
        const __nv_bfloat16* ql_g  = g_ql  + ((size_t)bh * SQ + m0) * DKH;
        const __nv_bfloat16* kh_g  = g_kh  + (size_t)bh * SQ * DKH;
        const __nv_bfloat16* kl_g  = g_kl  + (size_t)bh * SQ * DKH;
        const __nv_bfloat16* vth_g = g_vth + (size_t)bh * DKH * SQ;
        const __nv_bfloat16* vtl_g = g_vtl + (size_t)bh * DKH * SQ;

#pragma unroll
        for (int i = 0; i < 8; i++) {
            const int idx = tid + i * 256;
            const int arr = idx >> 10;
            const int r   = (idx >> 3) & 127;
            const int seg = idx & 7;
            const uint32_t dst = sb + arr * AT_QBYTES + r * 128 + ((seg ^ (r & 7)) << 4);
            const __nv_bfloat16* src = (arr ? ql_g : qh_g) + (size_t)r * DKH + seg * 8;
            cp_async16(dst, src);
        }

        auto load_stage = [&](int kt, int s) {
            const int n0 = kt * BC;
            const uint32_t sbase = sb + 2 * AT_QBYTES + s * AT_STAGE;
#pragma unroll
            for (int i = 0; i < 8; i++) {
                const int idx = tid + i * 256;
                const int arr = idx >> 9;
                const int r   = (idx >> 3) & 63;
                const int seg = idx & 7;
                const uint32_t dst = sbase + arr * 8192 + r * 128 + ((seg ^ (r & 7)) << 4);
                const __nv_bfloat16* src;
                if (arr == 0)      src = kh_g  + ((size_t)(n0 + r)) * DKH + seg * 8;
                else if (arr == 1) src = kl_g  + ((size_t)(n0 + r)) * DKH + seg * 8;
                else if (arr == 2) src = vth_g + (size_t)r * SQ + n0 + seg * 8;
                else               src = vtl_g + (size_t)r * SQ + n0 + seg * 8;
                cp_async16(dst, src);
            }
            CP_COMMIT();
        };

        load_stage(0, 0);
        load_stage(1, 1);

        float Oacc[8][4];
#pragma unroll
        for (int j = 0; j < 8; j++)
#pragma unroll
            for (int f = 0; f < 4; f++) Oacc[j][f] = 0.f;
        float m0r = -1e30f, m1r = -1e30f, l0r = 0.f, l1r = 0.f;

        for (int kt = 0; kt < NTK; kt++) {
            if (kt == NTK - 1) { CP_WAIT(0); } else { CP_WAIT(1); }
            __syncthreads();

            const uint32_t st  = sb + 2 * AT_QBYTES + (kt & 1) * AT_STAGE;
            const uint32_t sKh = st, sKl = st + 8192, sVh = st + 16384, sVl = st + 24576;

            float S[8][4];
#pragma unroll
            for (int j = 0; j < 8; j++)
#pragma unroll
                for (int f = 0; f < 4; f++) S[j][f] = 0.f;

#pragma unroll
            for (int ks = 0; ks < 4; ks++) {
                uint32_t aqh[4], aql[4];
                {
                    const uint32_t addr = sb + a_row * 128 +
                                          (((a_kseg + ks * 2) ^ (a_row & 7)) << 4);
                    LDSM_X4(aqh[0], aqh[1], aqh[2], aqh[3], addr);
                    const uint32_t addrl = addr + AT_QBYTES;
                    LDSM_X4(aql[0], aql[1], aql[2], aql[3], addrl);
                }
#pragma unroll
                for (int j2 = 0; j2 < 4; j2++) {
                    const int brow = j2 * 16 + b_rowc;
                    const uint32_t ksw = (((b_kseg + ks * 2) ^ (brow & 7)) << 4);
                    uint32_t bkh[4], bkl[4];
                    LDSM_X4(bkh[0], bkh[1], bkh[2], bkh[3], sKh + brow * 128 + ksw);
                    LDSM_X4(bkl[0], bkl[1], bkl[2], bkl[3], sKl + brow * 128 + ksw);
                    MMA_BF16(S[j2*2][0], S[j2*2][1], S[j2*2][2], S[j2*2][3],
                             aqh[0], aqh[1], aqh[2], aqh[3], bkh[0], bkh[1]);
                    MMA_BF16(S[j2*2+1][0], S[j2*2+1][1], S[j2*2+1][2], S[j2*2+1][3],
                             aqh[0], aqh[1], aqh[2], aqh[3], bkh[2], bkh[3]);
                    MMA_BF16(S[j2*2][0], S[j2*2][1], S[j2*2][2], S[j2*2][3],
                             aql[0], aql[1], aql[2], aql[3], bkh[0], bkh[1]);
                    MMA_BF16(S[j2*2+1][0], S[j2*2+1][1], S[j2*2+1][2], S[j2*2+1][3],
                             aql[0], aql[1], aql[2], aql[3], bkh[2], bkh[3]);
                    MMA_BF16(S[j2*2][0], S[j2*2][1], S[j2*2][2], S[j2*2][3],
                             aqh[0], aqh[1], aqh[2], aqh[3], bkl[0], bkl[1]);
                    MMA_BF16(S[j2*2+1][0], S[j2*2+1][1], S[j2*2+1][2], S[j2*2+1][3],
                             aqh[0], aqh[1], aqh[2], aqh[3], bkl[2], bkl[3]);
                }
            }

            float mx0 = -1e30f, mx1 = -1e30f;
#pragma unroll
            for (int j = 0; j < 8; j++) {
                mx0 = fmaxf(mx0, fmaxf(S[j][0], S[j][1]));
                mx1 = fmaxf(mx1, fmaxf(S[j][2], S[j][3]));
            }
            mx0 = fmaxf(mx0, __shfl_xor_sync(0xffffffffu, mx0, 1));
            mx0 = fmaxf(mx0, __shfl_xor_sync(0xffffffffu, mx0, 2));
            mx1 = fmaxf(mx1, __shfl_xor_sync(0xffffffffu, mx1, 1));
            mx1 = fmaxf(mx1, __shfl_xor_sync(0xffffffffu, mx1, 2));

            const float mn0 = fmaxf(m0r, mx0), mn1 = fmaxf(m1r, mx1);
            const float al0 = __expf(m0r - mn0), al1 = __expf(m1r - mn1);
            m0r = mn0; m1r = mn1;

            float ps0 = 0.f, ps1 = 0.f;
#pragma unroll
            for (int j = 0; j < 8; j++) {
                S[j][0] = __expf(S[j][0] - mn0); ps0 += S[j][0];
                S[j][1] = __expf(S[j][1] - mn0); ps0 += S[j][1];
                S[j][2] = __expf(S[j][2] - mn1); ps1 += S[j][2];
                S[j][3] = __expf(S[j][3] - mn1); ps1 += S[j][3];
            }
            l0r = l0r * al0 + ps0;
            l1r = l1r * al1 + ps1;
#pragma unroll
            for (int j = 0; j < 8; j++) {
                Oacc[j][0] *= al0; Oacc[j][1] *= al0;
                Oacc[j][2] *= al1; Oacc[j][3] *= al1;
            }

            // P fragments, hi and lo
            uint32_t aPh[4][4], aPl[4][4];
#pragma unroll
            for (int t = 0; t < 4; t++) {
                aPh[t][0] = pack_bf16(S[2*t][0],   S[2*t][1]);
                aPh[t][1] = pack_bf16(S[2*t][2],   S[2*t][3]);
                aPh[t][2] = pack_bf16(S[2*t+1][0], S[2*t+1][1]);
                aPh[t][3] = pack_bf16(S[2*t+1][2], S[2*t+1][3]);
                float2 h0 = unpack_bf16(aPh[t][0]);
                float2 h1 = unpack_bf16(aPh[t][1]);
                float2 h2 = unpack_bf16(aPh[t][2]);
                float2 h3 = unpack_bf16(aPh[t][3]);
                aPl[t][0] = pack_bf16(S[2*t][0]   - h0.x, S[2*t][1]   - h0.y);
                aPl[t][1] = pack_bf16(S[2*t][2]   - h1.x, S[2*t][3]   - h1.y);
                aPl[t][2] = pack_bf16(S[2*t+1][0] - h2.x, S[2*t+1][1] - h2.y);
                aPl[t][3] = pack_bf16(S[2*t+1][2] - h3.x, S[2*t+1][3] - h3.y);
            }

            // single-pass PV: ph*vh + ph*vl + pl*vh
#pragma unroll
            for (int t = 0; t < 4; t++) {
#pragma unroll
                for (int j2 = 0; j2 < 4; j2++) {
                    const int brow = j2 * 16 + b_rowc;
                    const uint32_t ksw = (((b_kseg + t * 2) ^ (brow & 7)) << 4);
                    uint32_t bvh[4], bvl[4];
                    LDSM_X4(bvh[0], bvh[1], bvh[2], bvh[3], sVh + brow * 128 + ksw);
                    LDSM_X4(bvl[0], bvl[1], bvl[2], bvl[3], sVl + brow * 128 + ksw);
                    MMA_BF16(Oacc[j2*2][0], Oacc[j2*2][1], Oacc[j2*2][2], Oacc[j2*2][3],
                             aPh[t][0], aPh[t][1], aPh[t][2], aPh[t][3], bvh[0], bvh[1]);
                    MMA_BF16(Oacc[j2*2+1][0], Oacc[j2*2+1][1], Oacc[j2*2+1][2], Oacc[j2*2+1][3],
                             aPh[t][0], aPh[t][1], aPh[t][2], aPh[t][3], bvh[2], bvh[3]);
                    MMA_BF16(Oacc[j2*2][0], Oacc[j2*2][1], Oacc[j2*2][2], Oacc[j2*2][3],
                             aPh[t][0], aPh[t][1], aPh[t][2], aPh[t][3], bvl[0], bvl[1]);
                    MMA_BF16(Oacc[j2*2+1][0], Oacc[j2*2+1][1], Oacc[j2*2+1][2], Oacc[j2*2+1][3],
                             aPh[t][0], aPh[t][1], aPh[t][2], aPh[t][3], bvl[2], bvl[3]);
                    MMA_BF16(Oacc[j2*2][0], Oacc[j2*2][1], Oacc[j2*2][2], Oacc[j2*2][3],
                             aPl[t][0], aPl[t][1], aPl[t][2], aPl[t][3], bvh[0], bvh[1]);
                    MMA_BF16(Oacc[j2*2+1][0], Oacc[j2*2+1][1], Oacc[j2*2+1][2], Oacc[j2*2+1][3],
                             aPl[t][0], aPl[t][1], aPl[t][2], aPl[t][3], bvh[2], bvh[3]);
                }
            }

            __syncthreads();
            if (kt + 2 < NTK) load_stage(kt + 2, kt & 1);
        }

        // finalize: write split-bf16 ctx into g_splitA slab 0 ([hi|lo], K2 wide)
        float t0 = l0r, t1 = l1r;
        t0 += __shfl_xor_sync(0xffffffffu, t0, 1);
        t0 += __shfl_xor_sync(0xffffffffu, t0, 2);
        t1 += __shfl_xor_sync(0xffffffffu, t1, 1);
        t1 += __shfl_xor_sync(0xffffffffu, t1, 2);
        const float inv0 = 1.f / t0, inv1 = 1.f / t1;

        const int r0 = lane >> 2;
        const size_t rowbase = (size_t)b * SQ + m0 + wid * 16;
#pragma unroll
        for (int j = 0; j < 8; j++) {
            const int col = h * DKH + (lane & 3) * 2 + j * 8;
#pragma unroll
            for (int rh = 0; rh < 2; rh++) {
                float2 v = (rh == 0)
                    ? make_float2(Oacc[j][0] * inv0, Oacc[j][1] * inv0)
                    : make_float2(Oacc[j][2] * inv1, Oacc[j][3] * inv1);
                __nv_bfloat162 hi = __float22bfloat162_rn(v);
                float2 hf = __bfloat1622float2(hi);
                __nv_bfloat162 lo = __float22bfloat162_rn(make_float2(v.x - hf.x, v.y - hf.y));
                const size_t m = rowbase + r0 + rh * 8;
                *reinterpret_cast<__nv_bfloat162*>(&g_splitA[m * K2 + col])          = hi;
                *reinterpret_cast<__nv_bfloat162*>(&g_splitA[m * K2 + DMODEL + col]) = lo;
            }
        }
    }
}

// ---------------------------------------------------------------------------
extern "C" void kernel_launch(void* const* d_in, const int* in_sizes, int n_in,
                              void* d_out, int out_size)
{
    const float* q  = (const float*)d_in[0];
    const float* k  = (const float*)d_in[1];
    const float* v  = (const float*)d_in[2];
    const float* Wq = (const float*)d_in[3];
    const float* bq = (const float*)d_in[4];
    const float* Wk = (const float*)d_in[5];
    const float* bk = (const float*)d_in[6];
    const float* Wv = (const float*)d_in[7];
    const float* bv = (const float*)d_in[8];
    const float* Wo = (const float*)d_in[9];
    const float* bo = (const float*)d_in[10];
    float* out = (float*)d_out;

    cudaFuncSetAttribute(flash_hmma_kernel,
                         cudaFuncAttributeMaxDynamicSharedMemorySize, ATTN_SMEM);
    cudaFuncSetAttribute(gemm_tc_kernel<0>,
                         cudaFuncAttributeMaxDynamicSharedMemorySize, GEMM_SMEM);
    cudaFuncSetAttribute(gemm_tc_kernel<1>,
                         cudaFuncAttributeMaxDynamicSharedMemorySize, GEMM_SMEM);

    // split all inputs and weights (2 launches)
    split_qkv_kernel<<<3 * 4096, 256>>>(q, k, v);
    split_w_kernel<<<4 * 1024, 256>>>(Wq, Wk, Wv, Wo);

    // batched QKV projections (1 launch, z = 0/1/2)
    dim3 qkv_grid(DMODEL / TN, MROWS / TM, 3);      // (8, 32, 3)
    gemm_tc_kernel<1><<<qkv_grid, 256, GEMM_SMEM>>>(bq, bk, bv, nullptr);

    // persistent attention (writes split ctx into g_splitA slab 0)
    flash_hmma_kernel<<<PGRID, 256, ATTN_SMEM>>>();

    // output projection
    dim3 out_grid(DMODEL / TN, MROWS / TM);         // (8, 32)
    gemm_tc_kernel<0><<<out_grid, 256, GEMM_SMEM>>>(bo, nullptr, nullptr, out);
}